// round 1
// baseline (speedup 1.0000x reference)
#include <cuda_runtime.h>
#include <math.h>

#define HID 128
#define CLS 10
#define NMAX 100000
#define EMAX 1600000
#define CMAX 50000
#define GMAX 64
#define HBITS 22
#define HSZ (1u << HBITS)
#define HMASK (HSZ - 1)
#define KEY_EMPTY 0xFFFFFFFFFFFFFFFFULL

// ---------------- scratch (device globals; no allocations allowed) ----------
__device__ __align__(256) float g_sum1[(size_t)NMAX * HID];
__device__ __align__(256) float g_sum2[(size_t)NMAX * HID];
__device__ __align__(256) float g_h1[(size_t)NMAX * HID];
__device__ __align__(256) float g_h2[(size_t)NMAX * HID];
__device__ int   g_deg[NMAX];
__device__ float g_invdeg[NMAX];
__device__ __align__(256) float g_xcsum[(size_t)CMAX * HID];
__device__ int   g_ccnt[CMAX];
__device__ __align__(256) float g_xc[(size_t)CMAX * HID];
__device__ __align__(256) float g_clsum[(size_t)CMAX * HID];
__device__ float g_clw[CMAX];
__device__ unsigned long long g_hkeys[HSZ];
__device__ float g_gsum[GMAX * CLS];
__device__ int   g_gcnt[GMAX];

// ---------------- helpers ----------------------------------------------------
__device__ __forceinline__ void red_add_v4(float* addr, float4 v) {
    asm volatile("red.global.add.v4.f32 [%0], {%1,%2,%3,%4};"
                 :: "l"(addr), "f"(v.x), "f"(v.y), "f"(v.z), "f"(v.w)
                 : "memory");
}

__device__ __forceinline__ unsigned hash64(unsigned long long k) {
    k ^= k >> 33; k *= 0xff51afd7ed558ccdULL;
    k ^= k >> 33; k *= 0xc4ceb9fe1a85ec53ULL;
    k ^= k >> 33;
    return (unsigned)k;
}

// ---------------- kernels ----------------------------------------------------
__global__ void deg_kernel(const int* __restrict__ dst, int E) {
    int i = blockIdx.x * blockDim.x + threadIdx.x;
    if (i < E) atomicAdd(&g_deg[dst[i]], 1);
}

__global__ void invdeg_kernel(int n) {
    int i = blockIdx.x * blockDim.x + threadIdx.x;
    if (i < n) {
        int d = g_deg[i];
        g_invdeg[i] = d > 0 ? 1.0f / (float)d : 0.0f;
    }
}

// one warp per edge: sums[dst] += feat[src]  (128 floats = 32 lanes x float4)
__global__ void edge_scatter_kernel(const float* __restrict__ feat,
                                    const int* __restrict__ src,
                                    const int* __restrict__ dst,
                                    float* __restrict__ sums, int E) {
    int w = (int)(((unsigned)blockIdx.x * blockDim.x + threadIdx.x) >> 5);
    if (w >= E) return;
    int lane = threadIdx.x & 31;
    int s = __ldg(src + w);
    int d = __ldg(dst + w);
    float4 v = *(const float4*)(feat + (size_t)s * HID + lane * 4);
    red_add_v4(sums + (size_t)d * HID + lane * 4, v);
}

// h = normalize(relu([agg | x] @ [Wl ; Wr] + b)), agg = sums * invdeg
// tile: 32 nodes x 128 cols x K=256, 256 threads, acc 4x4 per thread
__global__ __launch_bounds__(256) void node_layer_kernel(
    const float* __restrict__ xin, const float* __restrict__ sums,
    const float* __restrict__ Wl, const float* __restrict__ Wr,
    const float* __restrict__ b, float* __restrict__ hout, int n)
{
    __shared__ float As[32][32];
    __shared__ __align__(16) float Ws[32][HID];
    int tid = threadIdx.x;
    int tx = tid & 31;   // col group (4 cols)
    int ty = tid >> 5;   // node group (4 nodes)
    int block0 = blockIdx.x * 32;
    float acc[4][4] = {};

    for (int k0 = 0; k0 < 2 * HID; k0 += 32) {
        const float* W = (k0 < HID) ? Wl : Wr;
        int kb = (k0 < HID) ? k0 : (k0 - HID);
        // load A tile (virtual [agg | x])
        #pragma unroll
        for (int e = 0; e < 4; e++) {
            int idx = tid + e * 256;
            int nn = idx >> 5, kk = idx & 31;
            int node = block0 + nn;
            float v = 0.0f;
            if (node < n) {
                int k = k0 + kk;
                if (k < HID) v = sums[(size_t)node * HID + k] * g_invdeg[node];
                else         v = xin[(size_t)node * HID + (k - HID)];
            }
            As[nn][kk] = v;
        }
        // load W tile (32 x 128)
        #pragma unroll
        for (int e = 0; e < 4; e++) {
            int idx = tid + e * 256;
            int kk = idx >> 5, cc = (idx & 31) << 2;
            *(float4*)&Ws[kk][cc] = *(const float4*)(W + (size_t)(kb + kk) * HID + cc);
        }
        __syncthreads();
        #pragma unroll
        for (int kk = 0; kk < 32; kk++) {
            float4 w = *(float4*)&Ws[kk][tx << 2];
            float a0 = As[ty * 4 + 0][kk];
            float a1 = As[ty * 4 + 1][kk];
            float a2 = As[ty * 4 + 2][kk];
            float a3 = As[ty * 4 + 3][kk];
            acc[0][0] += a0 * w.x; acc[0][1] += a0 * w.y; acc[0][2] += a0 * w.z; acc[0][3] += a0 * w.w;
            acc[1][0] += a1 * w.x; acc[1][1] += a1 * w.y; acc[1][2] += a1 * w.z; acc[1][3] += a1 * w.w;
            acc[2][0] += a2 * w.x; acc[2][1] += a2 * w.y; acc[2][2] += a2 * w.z; acc[2][3] += a2 * w.w;
            acc[3][0] += a3 * w.x; acc[3][1] += a3 * w.y; acc[3][2] += a3 * w.z; acc[3][3] += a3 * w.w;
        }
        __syncthreads();
    }

    float4 bv = *(const float4*)(b + (tx << 2));
    #pragma unroll
    for (int i = 0; i < 4; i++) {
        float v0 = fmaxf(acc[i][0] + bv.x, 0.0f);
        float v1 = fmaxf(acc[i][1] + bv.y, 0.0f);
        float v2 = fmaxf(acc[i][2] + bv.z, 0.0f);
        float v3 = fmaxf(acc[i][3] + bv.w, 0.0f);
        float ss = v0 * v0 + v1 * v1 + v2 * v2 + v3 * v3;
        #pragma unroll
        for (int off = 16; off; off >>= 1) ss += __shfl_xor_sync(0xffffffffu, ss, off);
        float rn = rsqrtf(ss);
        int node = block0 + ty * 4 + i;
        if (node < n) {
            float4 o = make_float4(v0 * rn, v1 * rn, v2 * rn, v3 * rn);
            *(float4*)(hout + (size_t)node * HID + (tx << 2)) = o;
        }
    }
}

// cluster pooling: xcsum[c] += h2[node]; ccnt[c]++
__global__ void xc_scatter_kernel(const int* __restrict__ ca, int n) {
    int w = (int)(((unsigned)blockIdx.x * blockDim.x + threadIdx.x) >> 5);
    if (w >= n) return;
    int lane = threadIdx.x & 31;
    int c = __ldg(ca + w);
    float4 v = *(const float4*)(g_h2 + (size_t)w * HID + lane * 4);
    red_add_v4(g_xcsum + (size_t)c * HID + lane * 4, v);
    if (lane == 0) atomicAdd(&g_ccnt[c], 1);
}

__global__ void xc_final_kernel(int Cc) {
    int i = blockIdx.x * blockDim.x + threadIdx.x;  // over Cc*32 float4s
    if (i >= Cc * 32) return;
    int c = i >> 5;
    int cnt = g_ccnt[c];
    float inv = cnt > 0 ? 1.0f / (float)cnt : 0.0f;
    float4 s = *(const float4*)&g_xcsum[(size_t)i * 4];
    float4 o = make_float4(s.x * inv, s.y * inv, s.z * inv, s.w * inv);
    *(float4*)&g_xc[(size_t)i * 4] = o;
}

// dedup (cu,cv) pairs via lock-free hash; the inserting thread's warp scatters
// xc[cu] into clsum[cv] once per unique pair; clw[cv] counts unique pairs.
// (algebraically identical to the reference's 1/mult weighting)
__global__ void cluster_edge_kernel(const int* __restrict__ src,
                                    const int* __restrict__ dst,
                                    const int* __restrict__ ca, int E) {
    int w = (int)(((unsigned)blockIdx.x * blockDim.x + threadIdx.x) >> 5);
    if (w >= E) return;
    int lane = threadIdx.x & 31;
    int cu = 0, cv = 0, isnew = 0;
    if (lane == 0) {
        cu = ca[src[w]];
        cv = ca[dst[w]];
        unsigned long long key = ((unsigned long long)(unsigned)cu << 32) | (unsigned)cv;
        unsigned h = hash64(key) & HMASK;
        while (true) {
            unsigned long long old = atomicCAS(&g_hkeys[h], KEY_EMPTY, key);
            if (old == KEY_EMPTY) { isnew = 1; break; }
            if (old == key) break;
            h = (h + 1) & HMASK;
        }
    }
    isnew = __shfl_sync(0xffffffffu, isnew, 0);
    cu = __shfl_sync(0xffffffffu, cu, 0);
    cv = __shfl_sync(0xffffffffu, cv, 0);
    if (!isnew) return;
    float4 v = *(const float4*)(g_xc + (size_t)cu * HID + lane * 4);
    red_add_v4(g_clsum + (size_t)cv * HID + lane * 4, v);
    if (lane == 0) atomicAdd(&g_clw[cv], 1.0f);
}

// per-cluster: o = normalize(agg@Wl_out + xc@Wr_out + b_out); graph-pool it
__global__ __launch_bounds__(256) void cluster_out_kernel(
    const float* __restrict__ Wl, const float* __restrict__ Wr,
    const float* __restrict__ b, const int* __restrict__ bp, int Cc)
{
    __shared__ float WlS[HID * CLS];
    __shared__ float WrS[HID * CLS];
    __shared__ float bS[CLS];
    for (int i = threadIdx.x; i < HID * CLS; i += blockDim.x) {
        WlS[i] = Wl[i];
        WrS[i] = Wr[i];
    }
    if (threadIdx.x < CLS) bS[threadIdx.x] = b[threadIdx.x];
    __syncthreads();

    int w = (int)(((unsigned)blockIdx.x * blockDim.x + threadIdx.x) >> 5);
    if (w >= Cc) return;
    int lane = threadIdx.x & 31;
    float wsum = g_clw[w];
    float inv = wsum > 0.0f ? 1.0f / wsum : 0.0f;
    float c[CLS];
    #pragma unroll
    for (int j = 0; j < CLS; j++) c[j] = 0.0f;
    for (int k = lane; k < HID; k += 32) {
        float a  = g_clsum[(size_t)w * HID + k] * inv;
        float xv = g_xc[(size_t)w * HID + k];
        #pragma unroll
        for (int j = 0; j < CLS; j++) c[j] += a * WlS[k * CLS + j] + xv * WrS[k * CLS + j];
    }
    #pragma unroll
    for (int j = 0; j < CLS; j++) {
        #pragma unroll
        for (int off = 16; off; off >>= 1) c[j] += __shfl_xor_sync(0xffffffffu, c[j], off);
    }
    float ss = 0.0f;
    #pragma unroll
    for (int j = 0; j < CLS; j++) { c[j] += bS[j]; ss += c[j] * c[j]; }
    float rn = rsqrtf(ss);
    int g = __ldg(bp + w);
    #pragma unroll
    for (int j = 0; j < CLS; j++)
        if (lane == j) atomicAdd(&g_gsum[g * CLS + j], c[j] * rn);
    if (lane == 0) atomicAdd(&g_gcnt[g], 1);
}

__global__ void final_kernel(float* __restrict__ out, int G) {
    int g = blockIdx.x * blockDim.x + threadIdx.x;
    if (g >= G) return;
    int cnt = g_gcnt[g];
    float inv = cnt > 0 ? 1.0f / (float)cnt : 0.0f;
    float v[CLS];
    float mx = -1e30f;
    #pragma unroll
    for (int j = 0; j < CLS; j++) { v[j] = g_gsum[g * CLS + j] * inv; mx = fmaxf(mx, v[j]); }
    float s = 0.0f;
    #pragma unroll
    for (int j = 0; j < CLS; j++) s += expf(v[j] - mx);
    float lse = logf(s) + mx;
    #pragma unroll
    for (int j = 0; j < CLS; j++) out[g * CLS + j] = v[j] - lse;
}

// ---------------- launch ------------------------------------------------------
extern "C" void kernel_launch(void* const* d_in, const int* in_sizes, int n_in,
                              void* d_out, int out_size) {
    const float* x     = (const float*)d_in[0];
    const float* Wl_in = (const float*)d_in[1];
    const float* Wr_in = (const float*)d_in[2];
    const float* b_in  = (const float*)d_in[3];
    const float* Wl_h  = (const float*)d_in[4];
    const float* Wr_h  = (const float*)d_in[5];
    const float* b_h   = (const float*)d_in[6];
    const float* Wl_o  = (const float*)d_in[7];
    const float* Wr_o  = (const float*)d_in[8];
    const float* b_o   = (const float*)d_in[9];
    const int* esrc = (const int*)d_in[10];
    const int* edst = (const int*)d_in[11];
    const int* ca   = (const int*)d_in[12];
    const int* bp   = (const int*)d_in[13];

    int n  = in_sizes[0] / HID;
    int E  = in_sizes[10];
    int Cc = in_sizes[13];
    int G  = out_size / CLS;
    float* out = (float*)d_out;

    void* p;
    cudaGetSymbolAddress(&p, g_sum1);  cudaMemsetAsync(p, 0,    (size_t)n  * HID * sizeof(float));
    cudaGetSymbolAddress(&p, g_sum2);  cudaMemsetAsync(p, 0,    (size_t)n  * HID * sizeof(float));
    cudaGetSymbolAddress(&p, g_deg);   cudaMemsetAsync(p, 0,    (size_t)n  * sizeof(int));
    cudaGetSymbolAddress(&p, g_xcsum); cudaMemsetAsync(p, 0,    (size_t)Cc * HID * sizeof(float));
    cudaGetSymbolAddress(&p, g_ccnt);  cudaMemsetAsync(p, 0,    (size_t)Cc * sizeof(int));
    cudaGetSymbolAddress(&p, g_clsum); cudaMemsetAsync(p, 0,    (size_t)Cc * HID * sizeof(float));
    cudaGetSymbolAddress(&p, g_clw);   cudaMemsetAsync(p, 0,    (size_t)Cc * sizeof(float));
    cudaGetSymbolAddress(&p, g_hkeys); cudaMemsetAsync(p, 0xFF, (size_t)HSZ * sizeof(unsigned long long));
    cudaGetSymbolAddress(&p, g_gsum);  cudaMemsetAsync(p, 0,    (size_t)G * CLS * sizeof(float));
    cudaGetSymbolAddress(&p, g_gcnt);  cudaMemsetAsync(p, 0,    (size_t)G * sizeof(int));

    float *psum1, *psum2, *ph1, *ph2;
    cudaGetSymbolAddress((void**)&psum1, g_sum1);
    cudaGetSymbolAddress((void**)&psum2, g_sum2);
    cudaGetSymbolAddress((void**)&ph1,   g_h1);
    cudaGetSymbolAddress((void**)&ph2,   g_h2);

    int ewb = (E + 7) / 8;   // warp per edge, 8 warps/block
    deg_kernel<<<(E + 255) / 256, 256>>>(edst, E);
    invdeg_kernel<<<(n + 255) / 256, 256>>>(n);

    edge_scatter_kernel<<<ewb, 256>>>(x, esrc, edst, psum1, E);
    node_layer_kernel<<<(n + 31) / 32, 256>>>(x, psum1, Wl_in, Wr_in, b_in, ph1, n);

    edge_scatter_kernel<<<ewb, 256>>>(ph1, esrc, edst, psum2, E);
    node_layer_kernel<<<(n + 31) / 32, 256>>>(ph1, psum2, Wl_h, Wr_h, b_h, ph2, n);

    xc_scatter_kernel<<<(n + 7) / 8, 256>>>(ca, n);
    xc_final_kernel<<<(Cc * 32 + 255) / 256, 256>>>(Cc);

    cluster_edge_kernel<<<ewb, 256>>>(esrc, edst, ca, E);
    cluster_out_kernel<<<(Cc + 7) / 8, 256>>>(Wl_o, Wr_o, b_o, bp, Cc);

    final_kernel<<<(G + 63) / 64, 64>>>(out, G);
}

// round 2
// speedup vs baseline: 1.8940x; 1.8940x over previous
#include <cuda_runtime.h>
#include <math.h>

#define HID 128
#define CLS 10
#define NMAX 100000
#define EMAX 1600000
#define CMAX 50000
#define GMAX 64
#define HBITS 22
#define HSZ (1u << HBITS)
#define HMASK (HSZ - 1)
#define KEY_EMPTY 0xFFFFFFFFFFFFFFFFULL
#define SCAN_B 256

typedef unsigned long long ull;

// ---------------- scratch (device globals) -----------------------------------
__device__ __align__(256) float g_agg[(size_t)NMAX * HID];
__device__ __align__(256) float g_h1[(size_t)NMAX * HID];
__device__ __align__(256) float g_h2[(size_t)NMAX * HID];
__device__ __align__(256) float g_xc[(size_t)CMAX * HID];
__device__ int g_deg[NMAX];
__device__ int g_eoff[NMAX + 1];
__device__ int g_ecur[NMAX];
__device__ int g_esrt[EMAX];           // src ids sorted by dst
__device__ int g_ccnt[CMAX];
__device__ int g_coffc[CMAX + 1];
__device__ int g_ccur[CMAX];
__device__ int g_cnodes[NMAX];         // node ids sorted by cluster
__device__ int g_bsum[1024];
__device__ ull g_hkeys[HSZ];
__device__ float g_gsum[GMAX * CLS];
__device__ int g_gcnt[GMAX];

// ---------------- helpers ------------------------------------------------------
__device__ __forceinline__ unsigned hash64(ull k) {
    k ^= k >> 33; k *= 0xff51afd7ed558ccdULL;
    k ^= k >> 33; k *= 0xc4ceb9fe1a85ec53ULL;
    k ^= k >> 33;
    return (unsigned)k;
}

__device__ __forceinline__ ull pack2(float x) {
    unsigned u = __float_as_uint(x);
    return ((ull)u << 32) | (ull)u;
}
__device__ __forceinline__ float lo2(ull a) { return __uint_as_float((unsigned)a); }
__device__ __forceinline__ float hi2(ull a) { return __uint_as_float((unsigned)(a >> 32)); }

__device__ __forceinline__ void fma_x2(ull& d, ull a, ull b) {
    asm("fma.rn.f32x2 %0, %1, %2, %0;" : "+l"(d) : "l"(a), "l"(b));
}

// ---------------- histogram + scan + fill (CSR build) -------------------------
__global__ void deg_kernel(const int* __restrict__ dst, int E) {
    int i = blockIdx.x * blockDim.x + threadIdx.x;
    if (i < E) atomicAdd(&g_deg[dst[i]], 1);
}
__global__ void ccnt_kernel(const int* __restrict__ ca, int n) {
    int i = blockIdx.x * blockDim.x + threadIdx.x;
    if (i < n) atomicAdd(&g_ccnt[ca[i]], 1);
}

__global__ void scan_partial(const int* __restrict__ in, int* __restrict__ out,
                             int* __restrict__ bsum, int n) {
    __shared__ int sh[SCAN_B];
    int i = blockIdx.x * SCAN_B + threadIdx.x;
    int v = (i < n) ? in[i] : 0;
    sh[threadIdx.x] = v;
    __syncthreads();
    #pragma unroll
    for (int off = 1; off < SCAN_B; off <<= 1) {
        int t = (threadIdx.x >= off) ? sh[threadIdx.x - off] : 0;
        __syncthreads();
        sh[threadIdx.x] += t;
        __syncthreads();
    }
    if (i < n) out[i] = sh[threadIdx.x] - v;   // exclusive within block
    if (threadIdx.x == SCAN_B - 1) bsum[blockIdx.x] = sh[threadIdx.x];
}
__global__ void scan_bsums(int* __restrict__ bsum, int nb) {
    __shared__ int sh[1024];
    int v = (threadIdx.x < nb) ? bsum[threadIdx.x] : 0;
    sh[threadIdx.x] = v;
    __syncthreads();
    #pragma unroll
    for (int off = 1; off < 1024; off <<= 1) {
        int t = (threadIdx.x >= off) ? sh[threadIdx.x - off] : 0;
        __syncthreads();
        sh[threadIdx.x] += t;
        __syncthreads();
    }
    if (threadIdx.x < nb) bsum[threadIdx.x] = sh[threadIdx.x] - v;  // exclusive
}
__global__ void scan_add(const int* __restrict__ in, int* __restrict__ out,
                         const int* __restrict__ bsum, int n) {
    int i = blockIdx.x * SCAN_B + threadIdx.x;
    if (i < n) {
        int v = out[i] + bsum[blockIdx.x];
        out[i] = v;
        if (i == n - 1) out[n] = v + in[i];
    }
}

__global__ void fill_edges(const int* __restrict__ src, const int* __restrict__ dst, int E) {
    int i = blockIdx.x * blockDim.x + threadIdx.x;
    if (i >= E) return;
    int d = dst[i];
    int pos = atomicAdd(&g_ecur[d], 1);
    g_esrt[pos] = src[i];
}
__global__ void fill_cnodes(const int* __restrict__ ca, int n) {
    int i = blockIdx.x * blockDim.x + threadIdx.x;
    if (i >= n) return;
    int c = ca[i];
    int pos = atomicAdd(&g_ccur[c], 1);
    g_cnodes[pos] = i;
}

// ---------------- node aggregation: warp per node, gather-reduce --------------
__global__ void aggregate_kernel(const float* __restrict__ feat,
                                 float* __restrict__ agg, int n) {
    int w = (int)(((unsigned)blockIdx.x * blockDim.x + threadIdx.x) >> 5);
    if (w >= n) return;
    int lane = threadIdx.x & 31;
    int off = g_eoff[w], end = g_eoff[w + 1];
    float4 a0 = make_float4(0, 0, 0, 0), a1 = a0, a2 = a0, a3 = a0;
    int j = off;
    for (; j + 4 <= end; j += 4) {
        int s0 = __ldg(g_esrt + j + 0);
        int s1 = __ldg(g_esrt + j + 1);
        int s2 = __ldg(g_esrt + j + 2);
        int s3 = __ldg(g_esrt + j + 3);
        float4 v0 = *(const float4*)(feat + (size_t)s0 * HID + lane * 4);
        float4 v1 = *(const float4*)(feat + (size_t)s1 * HID + lane * 4);
        float4 v2 = *(const float4*)(feat + (size_t)s2 * HID + lane * 4);
        float4 v3 = *(const float4*)(feat + (size_t)s3 * HID + lane * 4);
        a0.x += v0.x; a0.y += v0.y; a0.z += v0.z; a0.w += v0.w;
        a1.x += v1.x; a1.y += v1.y; a1.z += v1.z; a1.w += v1.w;
        a2.x += v2.x; a2.y += v2.y; a2.z += v2.z; a2.w += v2.w;
        a3.x += v3.x; a3.y += v3.y; a3.z += v3.z; a3.w += v3.w;
    }
    for (; j < end; j++) {
        int s = __ldg(g_esrt + j);
        float4 v = *(const float4*)(feat + (size_t)s * HID + lane * 4);
        a0.x += v.x; a0.y += v.y; a0.z += v.z; a0.w += v.w;
    }
    float inv = (end > off) ? 1.0f / (float)(end - off) : 0.0f;
    float4 acc;
    acc.x = (a0.x + a1.x + a2.x + a3.x) * inv;
    acc.y = (a0.y + a1.y + a2.y + a3.y) * inv;
    acc.z = (a0.z + a1.z + a2.z + a3.z) * inv;
    acc.w = (a0.w + a1.w + a2.w + a3.w) * inv;
    *(float4*)(agg + (size_t)w * HID + lane * 4) = acc;
}

// ---------------- node layer GEMM: 128x128 tile, f32x2 FMAs --------------------
// h = normalize(relu([agg | x] @ [Wl ; Wr] + b))
#define GT 128
#define GKT 16
#define GKP 17

__global__ __launch_bounds__(256, 2) void node_layer_kernel(
    const float* __restrict__ agg, const float* __restrict__ xin,
    const float* __restrict__ Wl, const float* __restrict__ Wr,
    const float* __restrict__ bias, float* __restrict__ hout, int n)
{
    __shared__ __align__(16) ull As2[GT][GKP];     // A duplicated as f32x2 pairs
    __shared__ __align__(16) float Bs[GKT][HID];
    int tid = threadIdx.x;
    int tx = tid & 15;       // col group: 8 cols
    int ty = tid >> 4;       // row lane: rows ty + 16*i
    int n0 = blockIdx.x * GT;

    ull acc2[8][4] = {};

    for (int kt = 0; kt < 16; kt++) {
        const float* Asrc = (kt < 8) ? agg : xin;
        const float* Wsrc = (kt < 8) ? Wl : Wr;
        int kb = (kt & 7) * GKT;
        // A tile: 128 rows x 16 k
        #pragma unroll
        for (int e = 0; e < 2; e++) {
            int f = tid + e * 256;
            int r = f >> 2, kq = (f & 3) * 4;
            float4 v = make_float4(0, 0, 0, 0);
            if (n0 + r < n) v = *(const float4*)(Asrc + (size_t)(n0 + r) * HID + kb + kq);
            As2[r][kq + 0] = pack2(v.x);
            As2[r][kq + 1] = pack2(v.y);
            As2[r][kq + 2] = pack2(v.z);
            As2[r][kq + 3] = pack2(v.w);
        }
        // B tile: 16 k x 128 cols
        #pragma unroll
        for (int e = 0; e < 2; e++) {
            int f = tid + e * 256;
            int kk = f >> 5, cq = (f & 31) * 4;
            *(float4*)&Bs[kk][cq] = *(const float4*)(Wsrc + (size_t)(kb + kk) * HID + cq);
        }
        __syncthreads();
        #pragma unroll
        for (int k = 0; k < GKT; k++) {
            ull a2[8];
            #pragma unroll
            for (int i = 0; i < 8; i++) a2[i] = As2[ty + 16 * i][k];
            ulonglong2 p0 = *(ulonglong2*)&Bs[k][tx * 8];
            ulonglong2 p1 = *(ulonglong2*)&Bs[k][tx * 8 + 4];
            #pragma unroll
            for (int i = 0; i < 8; i++) {
                fma_x2(acc2[i][0], a2[i], p0.x);
                fma_x2(acc2[i][1], a2[i], p0.y);
                fma_x2(acc2[i][2], a2[i], p1.x);
                fma_x2(acc2[i][3], a2[i], p1.y);
            }
        }
        __syncthreads();
    }

    float bb[8];
    #pragma unroll
    for (int c = 0; c < 8; c++) bb[c] = bias[tx * 8 + c];

    #pragma unroll
    for (int i = 0; i < 8; i++) {
        float c[8];
        #pragma unroll
        for (int j = 0; j < 4; j++) {
            c[2 * j]     = lo2(acc2[i][j]);
            c[2 * j + 1] = hi2(acc2[i][j]);
        }
        float ss = 0.0f;
        #pragma unroll
        for (int q = 0; q < 8; q++) {
            c[q] = fmaxf(c[q] + bb[q], 0.0f);
            ss += c[q] * c[q];
        }
        ss += __shfl_xor_sync(0xffffffffu, ss, 1);
        ss += __shfl_xor_sync(0xffffffffu, ss, 2);
        ss += __shfl_xor_sync(0xffffffffu, ss, 4);
        ss += __shfl_xor_sync(0xffffffffu, ss, 8);
        float rn = rsqrtf(ss);
        int row = n0 + ty + 16 * i;
        if (row < n) {
            float4 o0 = make_float4(c[0] * rn, c[1] * rn, c[2] * rn, c[3] * rn);
            float4 o1 = make_float4(c[4] * rn, c[5] * rn, c[6] * rn, c[7] * rn);
            *(float4*)(hout + (size_t)row * HID + tx * 8)     = o0;
            *(float4*)(hout + (size_t)row * HID + tx * 8 + 4) = o1;
        }
    }
}

// ---------------- cluster mean: warp per cluster --------------------------------
__global__ void xc_kernel(int Cc) {
    int w = (int)(((unsigned)blockIdx.x * blockDim.x + threadIdx.x) >> 5);
    if (w >= Cc) return;
    int lane = threadIdx.x & 31;
    int mb = g_coffc[w], me = g_coffc[w + 1];
    float4 acc = make_float4(0, 0, 0, 0);
    for (int mi = mb; mi < me; mi++) {
        int node = g_cnodes[mi];
        float4 v = *(const float4*)(g_h2 + (size_t)node * HID + lane * 4);
        acc.x += v.x; acc.y += v.y; acc.z += v.z; acc.w += v.w;
    }
    float inv = (me > mb) ? 1.0f / (float)(me - mb) : 0.0f;
    acc.x *= inv; acc.y *= inv; acc.z *= inv; acc.w *= inv;
    *(float4*)(g_xc + (size_t)w * HID + lane * 4) = acc;
}

// ---------------- fused cluster layer: dedup + aggregate + GEMM + pool ----------
__global__ __launch_bounds__(256) void cluster_fused_kernel(
    const float* __restrict__ Wl, const float* __restrict__ Wr,
    const float* __restrict__ b, const int* __restrict__ ca,
    const int* __restrict__ bp, int Cc)
{
    __shared__ float WlS[HID * CLS];
    __shared__ float WrS[HID * CLS];
    __shared__ float bS[CLS];
    for (int i = threadIdx.x; i < HID * CLS; i += blockDim.x) {
        WlS[i] = Wl[i];
        WrS[i] = Wr[i];
    }
    if (threadIdx.x < CLS) bS[threadIdx.x] = b[threadIdx.x];
    __syncthreads();

    int w = (int)(((unsigned)blockIdx.x * blockDim.x + threadIdx.x) >> 5);
    if (w >= Cc) return;
    int lane = threadIdx.x & 31;

    float4 acc = make_float4(0, 0, 0, 0);
    int nuniq = 0;
    int mb = g_coffc[w], me = g_coffc[w + 1];
    for (int mi = mb; mi < me; mi++) {
        int node = g_cnodes[mi];
        int eb = g_eoff[node], ee = g_eoff[node + 1];
        for (int j0 = eb; j0 < ee; j0 += 32) {
            int j = j0 + lane;
            int isnew = 0, cu = 0;
            if (j < ee) {
                int s = g_esrt[j];
                cu = __ldg(ca + s);
                ull key = ((ull)(unsigned)cu << 32) | (unsigned)w;
                unsigned h = hash64(key) & HMASK;
                while (true) {
                    ull old = atomicCAS(&g_hkeys[h], KEY_EMPTY, key);
                    if (old == KEY_EMPTY) { isnew = 1; break; }
                    if (old == key) break;
                    h = (h + 1) & HMASK;
                }
            }
            unsigned m = __ballot_sync(0xffffffffu, isnew);
            nuniq += __popc(m);
            while (m) {
                int bpos = __ffs(m) - 1;
                m &= m - 1;
                int cuu = __shfl_sync(0xffffffffu, cu, bpos);
                float4 v = *(const float4*)(g_xc + (size_t)cuu * HID + lane * 4);
                acc.x += v.x; acc.y += v.y; acc.z += v.z; acc.w += v.w;
            }
        }
    }
    float inv = nuniq > 0 ? 1.0f / (float)nuniq : 0.0f;
    float4 a = make_float4(acc.x * inv, acc.y * inv, acc.z * inv, acc.w * inv);
    float4 xv = *(const float4*)(g_xc + (size_t)w * HID + lane * 4);

    float c[CLS];
    int k0 = lane * 4;
    #pragma unroll
    for (int j = 0; j < CLS; j++) {
        float s = a.x * WlS[(k0 + 0) * CLS + j] + xv.x * WrS[(k0 + 0) * CLS + j];
        s += a.y * WlS[(k0 + 1) * CLS + j] + xv.y * WrS[(k0 + 1) * CLS + j];
        s += a.z * WlS[(k0 + 2) * CLS + j] + xv.z * WrS[(k0 + 2) * CLS + j];
        s += a.w * WlS[(k0 + 3) * CLS + j] + xv.w * WrS[(k0 + 3) * CLS + j];
        c[j] = s;
    }
    #pragma unroll
    for (int j = 0; j < CLS; j++) {
        #pragma unroll
        for (int off = 16; off; off >>= 1)
            c[j] += __shfl_xor_sync(0xffffffffu, c[j], off);
    }
    float ss = 0.0f;
    #pragma unroll
    for (int j = 0; j < CLS; j++) { c[j] += bS[j]; ss += c[j] * c[j]; }
    float rn = rsqrtf(ss);
    int g = __ldg(bp + w);
    if (lane < CLS) atomicAdd(&g_gsum[g * CLS + lane], c[lane] * rn);
    if (lane == 0) atomicAdd(&g_gcnt[g], 1);
}

__global__ void final_kernel(float* __restrict__ out, int G) {
    int g = blockIdx.x * blockDim.x + threadIdx.x;
    if (g >= G) return;
    int cnt = g_gcnt[g];
    float inv = cnt > 0 ? 1.0f / (float)cnt : 0.0f;
    float v[CLS];
    float mx = -1e30f;
    #pragma unroll
    for (int j = 0; j < CLS; j++) { v[j] = g_gsum[g * CLS + j] * inv; mx = fmaxf(mx, v[j]); }
    float s = 0.0f;
    #pragma unroll
    for (int j = 0; j < CLS; j++) s += expf(v[j] - mx);
    float lse = logf(s) + mx;
    #pragma unroll
    for (int j = 0; j < CLS; j++) out[g * CLS + j] = v[j] - lse;
}

// ---------------- launch ---------------------------------------------------------
extern "C" void kernel_launch(void* const* d_in, const int* in_sizes, int n_in,
                              void* d_out, int out_size) {
    const float* x     = (const float*)d_in[0];
    const float* Wl_in = (const float*)d_in[1];
    const float* Wr_in = (const float*)d_in[2];
    const float* b_in  = (const float*)d_in[3];
    const float* Wl_h  = (const float*)d_in[4];
    const float* Wr_h  = (const float*)d_in[5];
    const float* b_h   = (const float*)d_in[6];
    const float* Wl_o  = (const float*)d_in[7];
    const float* Wr_o  = (const float*)d_in[8];
    const float* b_o   = (const float*)d_in[9];
    const int* esrc = (const int*)d_in[10];
    const int* edst = (const int*)d_in[11];
    const int* ca   = (const int*)d_in[12];
    const int* bp   = (const int*)d_in[13];

    int n  = in_sizes[0] / HID;
    int E  = in_sizes[10];
    int Cc = in_sizes[13];
    int G  = out_size / CLS;
    float* out = (float*)d_out;

    void *p_deg, *p_ccnt, *p_hkeys, *p_gsum, *p_gcnt;
    void *p_eoff, *p_ecur, *p_coffc, *p_ccur, *p_bsum;
    void *p_agg, *p_h1, *p_h2;
    cudaGetSymbolAddress(&p_deg,   g_deg);
    cudaGetSymbolAddress(&p_ccnt,  g_ccnt);
    cudaGetSymbolAddress(&p_hkeys, g_hkeys);
    cudaGetSymbolAddress(&p_gsum,  g_gsum);
    cudaGetSymbolAddress(&p_gcnt,  g_gcnt);
    cudaGetSymbolAddress(&p_eoff,  g_eoff);
    cudaGetSymbolAddress(&p_ecur,  g_ecur);
    cudaGetSymbolAddress(&p_coffc, g_coffc);
    cudaGetSymbolAddress(&p_ccur,  g_ccur);
    cudaGetSymbolAddress(&p_bsum,  g_bsum);
    cudaGetSymbolAddress(&p_agg,   g_agg);
    cudaGetSymbolAddress(&p_h1,    g_h1);
    cudaGetSymbolAddress(&p_h2,    g_h2);

    cudaMemsetAsync(p_deg,   0,    (size_t)n  * sizeof(int));
    cudaMemsetAsync(p_ccnt,  0,    (size_t)Cc * sizeof(int));
    cudaMemsetAsync(p_hkeys, 0xFF, (size_t)HSZ * sizeof(ull));
    cudaMemsetAsync(p_gsum,  0,    (size_t)G * CLS * sizeof(float));
    cudaMemsetAsync(p_gcnt,  0,    (size_t)G * sizeof(int));

    // histograms
    deg_kernel<<<(E + 255) / 256, 256>>>(edst, E);
    ccnt_kernel<<<(n + 255) / 256, 256>>>(ca, n);

    // edge CSR (by dst)
    int nbE = (n + SCAN_B - 1) / SCAN_B;
    scan_partial<<<nbE, SCAN_B>>>((const int*)p_deg, (int*)p_eoff, (int*)p_bsum, n);
    scan_bsums<<<1, 1024>>>((int*)p_bsum, nbE);
    scan_add<<<nbE, SCAN_B>>>((const int*)p_deg, (int*)p_eoff, (int*)p_bsum, n);
    cudaMemcpyAsync(p_ecur, p_eoff, (size_t)n * sizeof(int), cudaMemcpyDeviceToDevice);
    fill_edges<<<(E + 255) / 256, 256>>>(esrc, edst, E);

    // cluster-member CSR
    int nbC = (Cc + SCAN_B - 1) / SCAN_B;
    scan_partial<<<nbC, SCAN_B>>>((const int*)p_ccnt, (int*)p_coffc, (int*)p_bsum, Cc);
    scan_bsums<<<1, 1024>>>((int*)p_bsum, nbC);
    scan_add<<<nbC, SCAN_B>>>((const int*)p_ccnt, (int*)p_coffc, (int*)p_bsum, Cc);
    cudaMemcpyAsync(p_ccur, p_coffc, (size_t)Cc * sizeof(int), cudaMemcpyDeviceToDevice);
    fill_cnodes<<<(n + 255) / 256, 256>>>(ca, n);

    // layer 1
    aggregate_kernel<<<(n + 7) / 8, 256>>>(x, (float*)p_agg, n);
    node_layer_kernel<<<(n + GT - 1) / GT, 256>>>((const float*)p_agg, x,
                                                  Wl_in, Wr_in, b_in, (float*)p_h1, n);
    // layer 2
    aggregate_kernel<<<(n + 7) / 8, 256>>>((const float*)p_h1, (float*)p_agg, n);
    node_layer_kernel<<<(n + GT - 1) / GT, 256>>>((const float*)p_agg, (const float*)p_h1,
                                                  Wl_h, Wr_h, b_h, (float*)p_h2, n);

    // cluster stage
    xc_kernel<<<(Cc + 7) / 8, 256>>>(Cc);
    cluster_fused_kernel<<<(Cc + 7) / 8, 256>>>(Wl_o, Wr_o, b_o, ca, bp, Cc);

    final_kernel<<<(G + 63) / 64, 64>>>(out, G);
}

// round 3
// speedup vs baseline: 2.0876x; 1.1022x over previous
#include <cuda_runtime.h>
#include <math.h>

#define HID 128
#define CLS 10
#define NMAX 100000
#define EMAX 1600000
#define CMAX 50000
#define GMAX 64
#define SCAN_B 256
#define MTOT (NMAX + CMAX)

#define GT 128
#define GKT 16
#define GKP 17
#define AGP (HID + 4)
#define SMEM_AGG  (GT * AGP * 4)            // 67584
#define SMEM_AS2  (GT * GKP * 8)            // 17408
#define SMEM_BS   (GKT * HID * 4)           // 8192
#define SMEM_TOT  (SMEM_AGG + SMEM_AS2 + SMEM_BS)

typedef unsigned long long ull;

// ---------------- scratch (device globals) -----------------------------------
__device__ __align__(256) float g_h1[(size_t)NMAX * HID];
__device__ __align__(256) float g_h2[(size_t)NMAX * HID];
__device__ __align__(256) float g_xc[(size_t)CMAX * HID];
__device__ int g_cnt[MTOT];
__device__ int g_off[MTOT + 1];
__device__ int g_cur[MTOT];
__device__ int g_esrt[EMAX];           // src ids sorted by dst
__device__ int g_cnodes[NMAX];         // node ids sorted by cluster
__device__ int g_bsum[1024];
__device__ float g_gsum[GMAX * CLS];
__device__ int g_gcnt[GMAX];

// ---------------- helpers ------------------------------------------------------
__device__ __forceinline__ ull pack2(float x) {
    unsigned u = __float_as_uint(x);
    return ((ull)u << 32) | (ull)u;
}
__device__ __forceinline__ float lo2(ull a) { return __uint_as_float((unsigned)a); }
__device__ __forceinline__ float hi2(ull a) { return __uint_as_float((unsigned)(a >> 32)); }
__device__ __forceinline__ void fma_x2(ull& d, ull a, ull b) {
    asm("fma.rn.f32x2 %0, %1, %2, %0;" : "+l"(d) : "l"(a), "l"(b));
}

// ---------------- histogram (edges by dst + nodes by cluster, combined) --------
__global__ void count_kernel(const int* __restrict__ dst,
                             const int* __restrict__ ca, int E, int n) {
    int i = blockIdx.x * blockDim.x + threadIdx.x;
    if (i < E) atomicAdd(&g_cnt[dst[i]], 1);
    if (i < n) atomicAdd(&g_cnt[n + ca[i]], 1);
}

// ---------------- 3-phase exclusive scan over m = n + C ------------------------
__global__ void scan_partial(const int* __restrict__ in, int* __restrict__ out,
                             int* __restrict__ bsum, int m) {
    __shared__ int sh[SCAN_B];
    int i = blockIdx.x * SCAN_B + threadIdx.x;
    int v = (i < m) ? in[i] : 0;
    sh[threadIdx.x] = v;
    __syncthreads();
    #pragma unroll
    for (int off = 1; off < SCAN_B; off <<= 1) {
        int t = (threadIdx.x >= off) ? sh[threadIdx.x - off] : 0;
        __syncthreads();
        sh[threadIdx.x] += t;
        __syncthreads();
    }
    if (i < m) out[i] = sh[threadIdx.x] - v;
    if (threadIdx.x == SCAN_B - 1) bsum[blockIdx.x] = sh[threadIdx.x];
}
__global__ void scan_bsums(int* __restrict__ bsum, int nb) {
    __shared__ int sh[1024];
    int v = (threadIdx.x < nb) ? bsum[threadIdx.x] : 0;
    sh[threadIdx.x] = v;
    __syncthreads();
    #pragma unroll
    for (int off = 1; off < 1024; off <<= 1) {
        int t = (threadIdx.x >= off) ? sh[threadIdx.x - off] : 0;
        __syncthreads();
        sh[threadIdx.x] += t;
        __syncthreads();
    }
    if (threadIdx.x < nb) bsum[threadIdx.x] = sh[threadIdx.x] - v;
}
__global__ void scan_add(const int* __restrict__ in, int* __restrict__ out,
                         const int* __restrict__ bsum, int m) {
    int i = blockIdx.x * SCAN_B + threadIdx.x;
    if (i < m) {
        int v = out[i] + bsum[blockIdx.x];
        out[i] = v;
        if (i == m - 1) out[m] = v + in[i];
    }
}

// ---------------- fill both CSR payloads ----------------------------------------
__global__ void fill_kernel(const int* __restrict__ src, const int* __restrict__ dst,
                            const int* __restrict__ ca, int E, int n) {
    int i = blockIdx.x * blockDim.x + threadIdx.x;
    if (i < E) {
        int d = dst[i];
        int pos = atomicAdd(&g_cur[d], 1);
        g_esrt[pos] = src[i];
    }
    if (i < n) {
        int c = ca[i];
        int pos = atomicAdd(&g_cur[n + c], 1);
        g_cnodes[pos - E] = i;
    }
}

// ---------------- fused node layer: gather-mean + GEMM + relu + normalize ------
// h = normalize(relu([mean_{s in N(v)} x_s | x_v] @ [Wl ; Wr] + b))
__global__ __launch_bounds__(256, 2) void node_layer_fused(
    const float* __restrict__ xin, const float* __restrict__ Wl,
    const float* __restrict__ Wr, const float* __restrict__ bias,
    float* __restrict__ hout, int n)
{
    extern __shared__ char smem[];
    float (*aggS)[AGP] = (float(*)[AGP])smem;
    ull   (*As2)[GKP]  = (ull(*)[GKP])(smem + SMEM_AGG);
    float (*Bs)[HID]   = (float(*)[HID])(smem + SMEM_AGG + SMEM_AS2);

    int tid = threadIdx.x;
    int lane = tid & 31, wid = tid >> 5;
    int n0 = blockIdx.x * GT;

    // ---- gather phase: warp per node row, mean of neighbor features ----
    for (int r = wid; r < GT; r += 8) {
        int node = n0 + r;
        float4 acc = make_float4(0, 0, 0, 0);
        if (node < n) {
            int off = g_off[node], end = g_off[node + 1];
            int j = off;
            for (; j + 2 <= end; j += 2) {
                int s0 = __ldg(g_esrt + j);
                int s1 = __ldg(g_esrt + j + 1);
                float4 v0 = *(const float4*)(xin + (size_t)s0 * HID + lane * 4);
                float4 v1 = *(const float4*)(xin + (size_t)s1 * HID + lane * 4);
                acc.x += v0.x + v1.x; acc.y += v0.y + v1.y;
                acc.z += v0.z + v1.z; acc.w += v0.w + v1.w;
            }
            if (j < end) {
                int s = __ldg(g_esrt + j);
                float4 v = *(const float4*)(xin + (size_t)s * HID + lane * 4);
                acc.x += v.x; acc.y += v.y; acc.z += v.z; acc.w += v.w;
            }
            float inv = (end > off) ? 1.0f / (float)(end - off) : 0.0f;
            acc.x *= inv; acc.y *= inv; acc.z *= inv; acc.w *= inv;
        }
        *(float4*)&aggS[r][lane * 4] = acc;
    }
    __syncthreads();

    // ---- GEMM phase ----
    int tx = tid & 15;   // col group
    int ty = tid >> 4;   // row lane
    ull acc2[8][4] = {};

    for (int kt = 0; kt < 16; kt++) {
        // A tile -> As2 (duplicated f32x2)
        if (kt < 8) {
            int kb = kt * GKT;
            #pragma unroll
            for (int e = 0; e < 2; e++) {
                int f = tid + e * 256;
                int r = f >> 2, kq = (f & 3) * 4;
                float4 v = *(const float4*)&aggS[r][kb + kq];
                As2[r][kq + 0] = pack2(v.x);
                As2[r][kq + 1] = pack2(v.y);
                As2[r][kq + 2] = pack2(v.z);
                As2[r][kq + 3] = pack2(v.w);
            }
        } else {
            int kb = (kt - 8) * GKT;
            #pragma unroll
            for (int e = 0; e < 2; e++) {
                int f = tid + e * 256;
                int r = f >> 2, kq = (f & 3) * 4;
                float4 v = make_float4(0, 0, 0, 0);
                if (n0 + r < n) v = *(const float4*)(xin + (size_t)(n0 + r) * HID + kb + kq);
                As2[r][kq + 0] = pack2(v.x);
                As2[r][kq + 1] = pack2(v.y);
                As2[r][kq + 2] = pack2(v.z);
                As2[r][kq + 3] = pack2(v.w);
            }
        }
        // B tile
        {
            const float* W = (kt < 8) ? Wl : Wr;
            int kb = (kt & 7) * GKT;
            #pragma unroll
            for (int e = 0; e < 2; e++) {
                int f = tid + e * 256;
                int kk = f >> 5, cq = (f & 31) * 4;
                *(float4*)&Bs[kk][cq] = *(const float4*)(W + (size_t)(kb + kk) * HID + cq);
            }
        }
        __syncthreads();
        #pragma unroll
        for (int k = 0; k < GKT; k++) {
            ull a2[8];
            #pragma unroll
            for (int i = 0; i < 8; i++) a2[i] = As2[ty + 16 * i][k];
            // cols [tx*4, tx*4+3] and [64+tx*4, 64+tx*4+3] (contiguous per phase)
            ulonglong2 p0 = *(ulonglong2*)&Bs[k][tx * 4];
            ulonglong2 p1 = *(ulonglong2*)&Bs[k][64 + tx * 4];
            #pragma unroll
            for (int i = 0; i < 8; i++) {
                fma_x2(acc2[i][0], a2[i], p0.x);
                fma_x2(acc2[i][1], a2[i], p0.y);
                fma_x2(acc2[i][2], a2[i], p1.x);
                fma_x2(acc2[i][3], a2[i], p1.y);
            }
        }
        __syncthreads();
    }

    // ---- epilogue: bias + relu + row L2-normalize + store ----
    float4 bv0 = *(const float4*)(bias + tx * 4);
    float4 bv1 = *(const float4*)(bias + 64 + tx * 4);
    float bb[8] = {bv0.x, bv0.y, bv0.z, bv0.w, bv1.x, bv1.y, bv1.z, bv1.w};

    #pragma unroll
    for (int i = 0; i < 8; i++) {
        float c[8];
        #pragma unroll
        for (int j = 0; j < 4; j++) {
            c[2 * j]     = lo2(acc2[i][j]);
            c[2 * j + 1] = hi2(acc2[i][j]);
        }
        float ss = 0.0f;
        #pragma unroll
        for (int q = 0; q < 8; q++) {
            c[q] = fmaxf(c[q] + bb[q], 0.0f);
            ss += c[q] * c[q];
        }
        ss += __shfl_xor_sync(0xffffffffu, ss, 1);
        ss += __shfl_xor_sync(0xffffffffu, ss, 2);
        ss += __shfl_xor_sync(0xffffffffu, ss, 4);
        ss += __shfl_xor_sync(0xffffffffu, ss, 8);
        float rn = rsqrtf(ss);
        int row = n0 + ty + 16 * i;
        if (row < n) {
            float4 o0 = make_float4(c[0] * rn, c[1] * rn, c[2] * rn, c[3] * rn);
            float4 o1 = make_float4(c[4] * rn, c[5] * rn, c[6] * rn, c[7] * rn);
            *(float4*)(hout + (size_t)row * HID + tx * 4)      = o0;
            *(float4*)(hout + (size_t)row * HID + 64 + tx * 4) = o1;
        }
    }
}

// ---------------- cluster mean: warp per cluster --------------------------------
__global__ void xc_kernel(int n, int E, int Cc) {
    int w = (int)(((unsigned)blockIdx.x * blockDim.x + threadIdx.x) >> 5);
    if (w >= Cc) return;
    int lane = threadIdx.x & 31;
    int mb = g_off[n + w] - E, me = g_off[n + w + 1] - E;
    float4 acc = make_float4(0, 0, 0, 0);
    for (int mi = mb; mi < me; mi++) {
        int node = g_cnodes[mi];
        float4 v = *(const float4*)(g_h2 + (size_t)node * HID + lane * 4);
        acc.x += v.x; acc.y += v.y; acc.z += v.z; acc.w += v.w;
    }
    float inv = (me > mb) ? 1.0f / (float)(me - mb) : 0.0f;
    acc.x *= inv; acc.y *= inv; acc.z *= inv; acc.w *= inv;
    *(float4*)(g_xc + (size_t)w * HID + lane * 4) = acc;
}

// ---------------- fused cluster layer: SMEM-hash dedup + agg + GEMM + pool ------
__global__ __launch_bounds__(256) void cluster_fused_kernel(
    const float* __restrict__ Wl, const float* __restrict__ Wr,
    const float* __restrict__ b, const int* __restrict__ ca,
    const int* __restrict__ bp, int n, int E, int Cc)
{
    __shared__ float WlS[HID * CLS];
    __shared__ float WrS[HID * CLS];
    __shared__ float bS[CLS];
    __shared__ int hsh[8][512];

    int tid = threadIdx.x;
    int lane = tid & 31, wid = tid >> 5;

    for (int i = tid; i < HID * CLS; i += blockDim.x) {
        WlS[i] = Wl[i];
        WrS[i] = Wr[i];
    }
    if (tid < CLS) bS[tid] = b[tid];
    for (int i = lane; i < 512; i += 32) hsh[wid][i] = 0;
    __syncthreads();

    int w = (int)(((unsigned)blockIdx.x * blockDim.x + tid) >> 5);
    if (w >= Cc) return;

    float4 acc = make_float4(0, 0, 0, 0);
    int nuniq = 0;
    int mb = g_off[n + w] - E, me = g_off[n + w + 1] - E;
    for (int mi = mb; mi < me; mi++) {
        int node = g_cnodes[mi];
        int eb = g_off[node], ee = g_off[node + 1];
        for (int j0 = eb; j0 < ee; j0 += 32) {
            int j = j0 + lane;
            int isnew = 0, cu = 0;
            if (j < ee) {
                int s = g_esrt[j];
                cu = __ldg(ca + s);
                int key = cu + 1;
                unsigned h = ((unsigned)cu * 2654435761u) >> 23;
                h &= 511;
                while (true) {
                    int old = atomicCAS(&hsh[wid][h], 0, key);
                    if (old == 0) { isnew = 1; break; }
                    if (old == key) break;
                    h = (h + 1) & 511;
                }
            }
            unsigned m = __ballot_sync(0xffffffffu, isnew);
            nuniq += __popc(m);
            while (m) {
                int bpos = __ffs(m) - 1;
                m &= m - 1;
                int cuu = __shfl_sync(0xffffffffu, cu, bpos);
                float4 v = *(const float4*)(g_xc + (size_t)cuu * HID + lane * 4);
                acc.x += v.x; acc.y += v.y; acc.z += v.z; acc.w += v.w;
            }
        }
    }
    float inv = nuniq > 0 ? 1.0f / (float)nuniq : 0.0f;
    float4 a = make_float4(acc.x * inv, acc.y * inv, acc.z * inv, acc.w * inv);
    float4 xv = *(const float4*)(g_xc + (size_t)w * HID + lane * 4);

    float c[CLS];
    int k0 = lane * 4;
    #pragma unroll
    for (int j = 0; j < CLS; j++) {
        float s = a.x * WlS[(k0 + 0) * CLS + j] + xv.x * WrS[(k0 + 0) * CLS + j];
        s += a.y * WlS[(k0 + 1) * CLS + j] + xv.y * WrS[(k0 + 1) * CLS + j];
        s += a.z * WlS[(k0 + 2) * CLS + j] + xv.z * WrS[(k0 + 2) * CLS + j];
        s += a.w * WlS[(k0 + 3) * CLS + j] + xv.w * WrS[(k0 + 3) * CLS + j];
        c[j] = s;
    }
    #pragma unroll
    for (int j = 0; j < CLS; j++) {
        #pragma unroll
        for (int off = 16; off; off >>= 1)
            c[j] += __shfl_xor_sync(0xffffffffu, c[j], off);
    }
    float ss = 0.0f;
    #pragma unroll
    for (int j = 0; j < CLS; j++) { c[j] += bS[j]; ss += c[j] * c[j]; }
    float rn = rsqrtf(ss);
    int g = __ldg(bp + w);
    if (lane < CLS) atomicAdd(&g_gsum[g * CLS + lane], c[lane] * rn);
    if (lane == 0) atomicAdd(&g_gcnt[g], 1);
}

__global__ void final_kernel(float* __restrict__ out, int G) {
    int g = blockIdx.x * blockDim.x + threadIdx.x;
    if (g >= G) return;
    int cnt = g_gcnt[g];
    float inv = cnt > 0 ? 1.0f / (float)cnt : 0.0f;
    float v[CLS];
    float mx = -1e30f;
    #pragma unroll
    for (int j = 0; j < CLS; j++) { v[j] = g_gsum[g * CLS + j] * inv; mx = fmaxf(mx, v[j]); }
    float s = 0.0f;
    #pragma unroll
    for (int j = 0; j < CLS; j++) s += expf(v[j] - mx);
    float lse = logf(s) + mx;
    #pragma unroll
    for (int j = 0; j < CLS; j++) out[g * CLS + j] = v[j] - lse;
}

// ---------------- launch ---------------------------------------------------------
extern "C" void kernel_launch(void* const* d_in, const int* in_sizes, int n_in,
                              void* d_out, int out_size) {
    const float* x     = (const float*)d_in[0];
    const float* Wl_in = (const float*)d_in[1];
    const float* Wr_in = (const float*)d_in[2];
    const float* b_in  = (const float*)d_in[3];
    const float* Wl_h  = (const float*)d_in[4];
    const float* Wr_h  = (const float*)d_in[5];
    const float* b_h   = (const float*)d_in[6];
    const float* Wl_o  = (const float*)d_in[7];
    const float* Wr_o  = (const float*)d_in[8];
    const float* b_o   = (const float*)d_in[9];
    const int* esrc = (const int*)d_in[10];
    const int* edst = (const int*)d_in[11];
    const int* ca   = (const int*)d_in[12];
    const int* bp   = (const int*)d_in[13];

    int n  = in_sizes[0] / HID;
    int E  = in_sizes[10];
    int Cc = in_sizes[13];
    int G  = out_size / CLS;
    int m  = n + Cc;
    float* out = (float*)d_out;

    void *p_cnt, *p_off, *p_cur, *p_bsum, *p_gsum, *p_gcnt, *p_h1, *p_h2;
    cudaGetSymbolAddress(&p_cnt,  g_cnt);
    cudaGetSymbolAddress(&p_off,  g_off);
    cudaGetSymbolAddress(&p_cur,  g_cur);
    cudaGetSymbolAddress(&p_bsum, g_bsum);
    cudaGetSymbolAddress(&p_gsum, g_gsum);
    cudaGetSymbolAddress(&p_gcnt, g_gcnt);
    cudaGetSymbolAddress(&p_h1,   g_h1);
    cudaGetSymbolAddress(&p_h2,   g_h2);

    static int smem_set = 0;
    if (!smem_set) {
        cudaFuncSetAttribute(node_layer_fused,
                             cudaFuncAttributeMaxDynamicSharedMemorySize, SMEM_TOT);
        smem_set = 1;
    }

    cudaMemsetAsync(p_cnt,  0, (size_t)m * sizeof(int));
    cudaMemsetAsync(p_gsum, 0, (size_t)G * CLS * sizeof(float));
    cudaMemsetAsync(p_gcnt, 0, (size_t)G * sizeof(int));

    // combined CSR build (edges by dst + nodes by cluster)
    int cover = (E > n) ? E : n;
    count_kernel<<<(cover + 255) / 256, 256>>>(edst, ca, E, n);
    int nb = (m + SCAN_B - 1) / SCAN_B;
    scan_partial<<<nb, SCAN_B>>>((const int*)p_cnt, (int*)p_off, (int*)p_bsum, m);
    scan_bsums<<<1, 1024>>>((int*)p_bsum, nb);
    scan_add<<<nb, SCAN_B>>>((const int*)p_cnt, (int*)p_off, (int*)p_bsum, m);
    cudaMemcpyAsync(p_cur, p_off, (size_t)m * sizeof(int), cudaMemcpyDeviceToDevice);
    fill_kernel<<<(cover + 255) / 256, 256>>>(esrc, edst, ca, E, n);

    // two fused SAGE layers
    int gblocks = (n + GT - 1) / GT;
    node_layer_fused<<<gblocks, 256, SMEM_TOT>>>(x, Wl_in, Wr_in, b_in, (float*)p_h1, n);
    node_layer_fused<<<gblocks, 256, SMEM_TOT>>>((const float*)p_h1, Wl_h, Wr_h, b_h,
                                                 (float*)p_h2, n);

    // cluster stage
    xc_kernel<<<(Cc + 7) / 8, 256>>>(n, E, Cc);
    cluster_fused_kernel<<<(Cc + 7) / 8, 256>>>(Wl_o, Wr_o, b_o, ca, bp, n, E, Cc);

    final_kernel<<<(G + 63) / 64, 64>>>(out, G);
}

// round 4
// speedup vs baseline: 2.6618x; 1.2750x over previous
#include <cuda_runtime.h>
#include <cuda_bf16.h>
#include <math.h>
#include <stdint.h>

#define HID 128
#define CLS 10
#define NMAX 100000
#define EMAX 1600000
#define CMAX 50000
#define GMAX 64
#define SCAN_B 256
#define MTOT (NMAX + CMAX)

typedef unsigned long long ull;

// ---------------- scratch (device globals) -----------------------------------
__device__ __align__(256) float g_h1[(size_t)NMAX * HID];   // fp32 layer-1 output
__device__ __align__(256) float g_h2[(size_t)NMAX * HID];   // fp32 layer-2 output
__device__ __align__(256) float g_xc[(size_t)CMAX * HID];   // fp32 cluster means
__device__ __align__(16) uint32_t g_xb [(size_t)NMAX * 64]; // bf16 x table
__device__ __align__(16) uint32_t g_h1b[(size_t)NMAX * 64]; // bf16 h1 table
__device__ __align__(16) uint32_t g_xcb[(size_t)CMAX * 64]; // bf16 xc table
__device__ __align__(16) float2 g_bfrag[4 * 16 * 16 * 32];  // tf32 B fragments
__device__ int g_cnt[MTOT];
__device__ int g_off[MTOT + 1];
__device__ int g_cur[MTOT];
__device__ int g_esrt[EMAX];           // src ids sorted by dst
__device__ int g_cnodes[NMAX];         // node ids sorted by cluster
__device__ int g_bsum[1024];
__device__ float g_gsum[GMAX * CLS];
__device__ int g_gcnt[GMAX];

// ---------------- helpers ------------------------------------------------------
__device__ __forceinline__ float tf32r(float f) {
    uint32_t o;
    asm("cvt.rna.tf32.f32 %0, %1;" : "=r"(o) : "f"(f));
    return __uint_as_float(o);
}

__device__ __forceinline__ void mma8(float d[4], const unsigned a[4],
                                     unsigned b0, unsigned b1) {
    asm volatile("mma.sync.aligned.m16n8k8.row.col.f32.tf32.tf32.f32 "
                 "{%0,%1,%2,%3}, {%4,%5,%6,%7}, {%8,%9}, {%0,%1,%2,%3};"
                 : "+f"(d[0]), "+f"(d[1]), "+f"(d[2]), "+f"(d[3])
                 : "r"(a[0]), "r"(a[1]), "r"(a[2]), "r"(a[3]), "r"(b0), "r"(b1));
}

__device__ __forceinline__ void bf16acc(float4& acc, uint2 u) {
    float2 p = __bfloat1622float2(*(__nv_bfloat162*)&u.x);
    float2 q = __bfloat1622float2(*(__nv_bfloat162*)&u.y);
    acc.x += p.x; acc.y += p.y; acc.z += q.x; acc.w += q.y;
}

// ---------------- prep kernels ---------------------------------------------------
// B fragments: g_bfrag[mat][ks 16][nt 16][lane 32] -> (b0,b1) tf32
__global__ void prep_bfrag(const float* __restrict__ W0, const float* __restrict__ W1,
                           const float* __restrict__ W2, const float* __restrict__ W3) {
    int i = blockIdx.x * blockDim.x + threadIdx.x;
    if (i >= 4 * 16 * 16 * 32) return;
    int lane = i & 31, nt = (i >> 5) & 15, ks = (i >> 9) & 15, mat = i >> 13;
    const float* W = (mat == 0) ? W0 : (mat == 1) ? W1 : (mat == 2) ? W2 : W3;
    int k0 = ks * 8 + (lane & 3);
    int nn = nt * 8 + (lane >> 2);
    float2 o;
    o.x = tf32r(W[(size_t)k0 * HID + nn]);
    o.y = tf32r(W[(size_t)(k0 + 4) * HID + nn]);
    g_bfrag[i] = o;
}

// fp32 rows -> bf16 table (thread per 4 elements)
__global__ void prep_xb(const float* __restrict__ src, uint2* __restrict__ dst, int cnt) {
    int i = blockIdx.x * blockDim.x + threadIdx.x;
    if (i >= cnt) return;
    float4 v = *(const float4*)(src + (size_t)i * 4);
    __nv_bfloat162 lo = __floats2bfloat162_rn(v.x, v.y);
    __nv_bfloat162 hi = __floats2bfloat162_rn(v.z, v.w);
    uint2 o;
    o.x = *(uint32_t*)&lo;
    o.y = *(uint32_t*)&hi;
    dst[i] = o;
}

// ---------------- histogram + scan + fill (combined CSRs) -----------------------
__global__ void count_kernel(const int* __restrict__ dst,
                             const int* __restrict__ ca, int E, int n) {
    int i = blockIdx.x * blockDim.x + threadIdx.x;
    if (i < E) atomicAdd(&g_cnt[dst[i]], 1);
    if (i < n) atomicAdd(&g_cnt[n + ca[i]], 1);
}
__global__ void scan_partial(const int* __restrict__ in, int* __restrict__ out,
                             int* __restrict__ bsum, int m) {
    __shared__ int sh[SCAN_B];
    int i = blockIdx.x * SCAN_B + threadIdx.x;
    int v = (i < m) ? in[i] : 0;
    sh[threadIdx.x] = v;
    __syncthreads();
    #pragma unroll
    for (int off = 1; off < SCAN_B; off <<= 1) {
        int t = (threadIdx.x >= off) ? sh[threadIdx.x - off] : 0;
        __syncthreads();
        sh[threadIdx.x] += t;
        __syncthreads();
    }
    if (i < m) out[i] = sh[threadIdx.x] - v;
    if (threadIdx.x == SCAN_B - 1) bsum[blockIdx.x] = sh[threadIdx.x];
}
__global__ void scan_bsums(int* __restrict__ bsum, int nb) {
    __shared__ int sh[1024];
    int v = (threadIdx.x < nb) ? bsum[threadIdx.x] : 0;
    sh[threadIdx.x] = v;
    __syncthreads();
    #pragma unroll
    for (int off = 1; off < 1024; off <<= 1) {
        int t = (threadIdx.x >= off) ? sh[threadIdx.x - off] : 0;
        __syncthreads();
        sh[threadIdx.x] += t;
        __syncthreads();
    }
    if (threadIdx.x < nb) bsum[threadIdx.x] = sh[threadIdx.x] - v;
}
__global__ void scan_add(const int* __restrict__ in, int* __restrict__ out,
                         const int* __restrict__ bsum, int m) {
    int i = blockIdx.x * SCAN_B + threadIdx.x;
    if (i < m) {
        int v = out[i] + bsum[blockIdx.x];
        out[i] = v;
        if (i == m - 1) out[m] = v + in[i];
    }
}
__global__ void fill_kernel(const int* __restrict__ src, const int* __restrict__ dst,
                            const int* __restrict__ ca, int E, int n) {
    int i = blockIdx.x * blockDim.x + threadIdx.x;
    if (i < E) {
        int d = dst[i];
        int pos = atomicAdd(&g_cur[d], 1);
        g_esrt[pos] = src[i];
    }
    if (i < n) {
        int c = ca[i];
        int pos = atomicAdd(&g_cur[n + c], 1);
        g_cnodes[pos - E] = i;
    }
}

// ---------------- fused node layer: bf16 gather -> tf32 MMA -> norm -------------
// Smem layout (floats): [0,16384) agg A-fragments (16 ksteps x 8 mtiles x 32 x 4)
//                       [16384,20480) x-chunk A-fragments (4 x 8 x 32 x 4)
//                       [20480,20608) row sum-of-squares
#define AFRAG(ks, mt, ln) ((((ks) * 8 + (mt)) * 32 + (ln)) * 4)
#define SMEM_NODE ((16384 + 4096 + 128) * 4)

__global__ __launch_bounds__(256, 2) void node_layer_fused(
    const uint2* __restrict__ xb, const float* __restrict__ xin,
    const float2* __restrict__ bfragL, const float2* __restrict__ bfragR,
    const float* __restrict__ bias,
    float* __restrict__ hout, uint32_t* __restrict__ houtb, int n)
{
    extern __shared__ float sm[];
    float* smx   = sm + 16384;
    float* rowss = sm + 16384 + 4096;
    int tid = threadIdx.x, lane = tid & 31, wid = tid >> 5;
    int n0 = blockIdx.x * 128;
    if (tid < 128) rowss[tid] = 0.0f;

    // ---- gather phase: warp per row, mean of bf16 neighbor rows, write A-frags ----
    for (int r = wid; r < 128; r += 8) {
        int node = n0 + r;
        float4 acc = make_float4(0, 0, 0, 0);
        if (node < n) {
            int off = g_off[node], end = g_off[node + 1];
            int j = off;
            for (; j + 4 <= end; j += 4) {
                int s0 = __ldg(g_esrt + j + 0);
                int s1 = __ldg(g_esrt + j + 1);
                int s2 = __ldg(g_esrt + j + 2);
                int s3 = __ldg(g_esrt + j + 3);
                uint2 u0 = __ldg(xb + (size_t)s0 * 32 + lane);
                uint2 u1 = __ldg(xb + (size_t)s1 * 32 + lane);
                uint2 u2 = __ldg(xb + (size_t)s2 * 32 + lane);
                uint2 u3 = __ldg(xb + (size_t)s3 * 32 + lane);
                bf16acc(acc, u0); bf16acc(acc, u1);
                bf16acc(acc, u2); bf16acc(acc, u3);
            }
            for (; j < end; j++) {
                int s = __ldg(g_esrt + j);
                bf16acc(acc, __ldg(xb + (size_t)s * 32 + lane));
            }
            float inv = (end > off) ? 1.0f / (float)(end - off) : 0.0f;
            acc.x *= inv; acc.y *= inv; acc.z *= inv; acc.w *= inv;
        }
        // fragment-layout write: lane covers cols 4*lane..4*lane+3
        int mt = r >> 4, w = r & 15, hi = w >> 3, wr = w & 7;
        int comp = 2 * (lane & 1) + hi;
        int kk = lane >> 1;
        float v[4] = {acc.x, acc.y, acc.z, acc.w};
        #pragma unroll
        for (int q = 0; q < 4; q++)
            sm[AFRAG(kk, mt, (wr << 2) | q) + comp] = tf32r(v[q]);
    }
    __syncthreads();

    // ---- MMA phase ----
    int warp_m = wid >> 2, warp_n = wid & 3;
    float d[4][4][4] = {};

    // half 1: agg @ Wl  (A-frags resident in smem)
    #pragma unroll 2
    for (int ks = 0; ks < 16; ks++) {
        unsigned a[4][4];
        #pragma unroll
        for (int t = 0; t < 4; t++) {
            float4 v = *(float4*)&sm[AFRAG(ks, warp_m * 4 + t, lane)];
            a[t][0] = __float_as_uint(v.x); a[t][1] = __float_as_uint(v.y);
            a[t][2] = __float_as_uint(v.z); a[t][3] = __float_as_uint(v.w);
        }
        #pragma unroll
        for (int u = 0; u < 4; u++) {
            float2 bv = __ldg(&bfragL[(size_t)(ks * 16 + warp_n * 4 + u) * 32 + lane]);
            unsigned b0 = __float_as_uint(bv.x), b1 = __float_as_uint(bv.y);
            #pragma unroll
            for (int t = 0; t < 4; t++) mma8(d[t][u], a[t], b0, b1);
        }
    }

    // half 2: x @ Wr (stage 32-k chunks from global fp32)
    for (int cc = 0; cc < 4; cc++) {
        __syncthreads();
        #pragma unroll
        for (int e = 0; e < 4; e++) {
            int s = tid + e * 256;
            int kk = s >> 8, mt = (s >> 5) & 7, l = s & 31;
            int r = n0 + mt * 16 + (l >> 2);
            int c = cc * 32 + kk * 8 + (l & 3);
            float v0 = 0, v1 = 0, v2 = 0, v3 = 0;
            if (r < n)     { v0 = xin[(size_t)r * HID + c];       v2 = xin[(size_t)r * HID + c + 4]; }
            if (r + 8 < n) { v1 = xin[(size_t)(r + 8) * HID + c]; v3 = xin[(size_t)(r + 8) * HID + c + 4]; }
            float4 o = make_float4(tf32r(v0), tf32r(v1), tf32r(v2), tf32r(v3));
            *(float4*)&smx[AFRAG(kk, mt, l)] = o;
        }
        __syncthreads();
        #pragma unroll
        for (int kk = 0; kk < 4; kk++) {
            unsigned a[4][4];
            #pragma unroll
            for (int t = 0; t < 4; t++) {
                float4 v = *(float4*)&smx[AFRAG(kk, warp_m * 4 + t, lane)];
                a[t][0] = __float_as_uint(v.x); a[t][1] = __float_as_uint(v.y);
                a[t][2] = __float_as_uint(v.z); a[t][3] = __float_as_uint(v.w);
            }
            int ksg = cc * 4 + kk;
            #pragma unroll
            for (int u = 0; u < 4; u++) {
                float2 bv = __ldg(&bfragR[(size_t)(ksg * 16 + warp_n * 4 + u) * 32 + lane]);
                unsigned b0 = __float_as_uint(bv.x), b1 = __float_as_uint(bv.y);
                #pragma unroll
                for (int t = 0; t < 4; t++) mma8(d[t][u], a[t], b0, b1);
            }
        }
    }

    // ---- epilogue: bias + relu, cross-warp row-norm, store fp32 + bf16 ----
    float2 bb[4];
    #pragma unroll
    for (int u = 0; u < 4; u++)
        bb[u] = *(const float2*)(bias + warp_n * 32 + u * 8 + (lane & 3) * 2);

    #pragma unroll
    for (int t = 0; t < 4; t++) {
        float ss0 = 0, ss1 = 0;
        #pragma unroll
        for (int u = 0; u < 4; u++) {
            float c0 = fmaxf(d[t][u][0] + bb[u].x, 0.0f);
            float c1 = fmaxf(d[t][u][1] + bb[u].y, 0.0f);
            float c2 = fmaxf(d[t][u][2] + bb[u].x, 0.0f);
            float c3 = fmaxf(d[t][u][3] + bb[u].y, 0.0f);
            ss0 += c0 * c0 + c1 * c1;
            ss1 += c2 * c2 + c3 * c3;
            d[t][u][0] = c0; d[t][u][1] = c1; d[t][u][2] = c2; d[t][u][3] = c3;
        }
        int lr = warp_m * 64 + t * 16 + (lane >> 2);
        atomicAdd(&rowss[lr], ss0);
        atomicAdd(&rowss[lr + 8], ss1);
    }
    __syncthreads();

    #pragma unroll
    for (int t = 0; t < 4; t++) {
        int lr = warp_m * 64 + t * 16 + (lane >> 2);
        int r0 = n0 + lr;
        float rn0 = rsqrtf(rowss[lr]);
        float rn1 = rsqrtf(rowss[lr + 8]);
        #pragma unroll
        for (int u = 0; u < 4; u++) {
            int cb = warp_n * 32 + u * 8 + (lane & 3) * 2;
            if (r0 < n) {
                float o0 = d[t][u][0] * rn0, o1 = d[t][u][1] * rn0;
                *(float2*)&hout[(size_t)r0 * HID + cb] = make_float2(o0, o1);
                __nv_bfloat162 bh = __floats2bfloat162_rn(o0, o1);
                houtb[(size_t)r0 * 64 + (cb >> 1)] = *(uint32_t*)&bh;
            }
            if (r0 + 8 < n) {
                float o0 = d[t][u][2] * rn1, o1 = d[t][u][3] * rn1;
                *(float2*)&hout[(size_t)(r0 + 8) * HID + cb] = make_float2(o0, o1);
                __nv_bfloat162 bh = __floats2bfloat162_rn(o0, o1);
                houtb[(size_t)(r0 + 8) * 64 + (cb >> 1)] = *(uint32_t*)&bh;
            }
        }
    }
}

// ---------------- cluster mean: warp per cluster --------------------------------
__global__ void xc_kernel(int n, int E, int Cc) {
    int w = (int)(((unsigned)blockIdx.x * blockDim.x + threadIdx.x) >> 5);
    if (w >= Cc) return;
    int lane = threadIdx.x & 31;
    int mb = g_off[n + w] - E, me = g_off[n + w + 1] - E;
    float4 acc = make_float4(0, 0, 0, 0);
    for (int mi = mb; mi < me; mi++) {
        int node = g_cnodes[mi];
        float4 v = *(const float4*)(g_h2 + (size_t)node * HID + lane * 4);
        acc.x += v.x; acc.y += v.y; acc.z += v.z; acc.w += v.w;
    }
    float inv = (me > mb) ? 1.0f / (float)(me - mb) : 0.0f;
    acc.x *= inv; acc.y *= inv; acc.z *= inv; acc.w *= inv;
    *(float4*)(g_xc + (size_t)w * HID + lane * 4) = acc;
    __nv_bfloat162 lo = __floats2bfloat162_rn(acc.x, acc.y);
    __nv_bfloat162 hi = __floats2bfloat162_rn(acc.z, acc.w);
    uint2 o;
    o.x = *(uint32_t*)&lo;
    o.y = *(uint32_t*)&hi;
    *(uint2*)&g_xcb[(size_t)w * 64 + lane * 2] = o;
}

// ---------------- fused cluster layer: SMEM-hash dedup + agg + GEMM + pool ------
__global__ __launch_bounds__(256) void cluster_fused_kernel(
    const float* __restrict__ Wl, const float* __restrict__ Wr,
    const float* __restrict__ b, const int* __restrict__ ca,
    const int* __restrict__ bp, int n, int E, int Cc)
{
    __shared__ float WlS[HID * CLS];
    __shared__ float WrS[HID * CLS];
    __shared__ float bS[CLS];
    __shared__ int hsh[8][512];

    int tid = threadIdx.x;
    int lane = tid & 31, wid = tid >> 5;

    for (int i = tid; i < HID * CLS; i += blockDim.x) {
        WlS[i] = Wl[i];
        WrS[i] = Wr[i];
    }
    if (tid < CLS) bS[tid] = b[tid];
    for (int i = lane; i < 512; i += 32) hsh[wid][i] = 0;
    __syncthreads();

    int w = (int)(((unsigned)blockIdx.x * blockDim.x + tid) >> 5);
    if (w >= Cc) return;

    const uint2* xcb = (const uint2*)g_xcb;
    float4 acc = make_float4(0, 0, 0, 0);
    int nuniq = 0;
    int mb = g_off[n + w] - E, me = g_off[n + w + 1] - E;
    for (int mi = mb; mi < me; mi++) {
        int node = g_cnodes[mi];
        int eb = g_off[node], ee = g_off[node + 1];
        for (int j0 = eb; j0 < ee; j0 += 32) {
            int j = j0 + lane;
            int isnew = 0, cu = 0;
            if (j < ee) {
                int s = g_esrt[j];
                cu = __ldg(ca + s);
                int key = cu + 1;
                unsigned h = ((unsigned)cu * 2654435761u) >> 23;
                h &= 511;
                while (true) {
                    int old = atomicCAS(&hsh[wid][h], 0, key);
                    if (old == 0) { isnew = 1; break; }
                    if (old == key) break;
                    h = (h + 1) & 511;
                }
            }
            unsigned m = __ballot_sync(0xffffffffu, isnew);
            nuniq += __popc(m);
            while (m) {
                int bpos = __ffs(m) - 1;
                m &= m - 1;
                int cuu = __shfl_sync(0xffffffffu, cu, bpos);
                bf16acc(acc, __ldg(xcb + (size_t)cuu * 32 + lane));
            }
        }
    }
    float inv = nuniq > 0 ? 1.0f / (float)nuniq : 0.0f;
    float4 a = make_float4(acc.x * inv, acc.y * inv, acc.z * inv, acc.w * inv);
    float4 xv = *(const float4*)(g_xc + (size_t)w * HID + lane * 4);

    float c[CLS];
    int k0 = lane * 4;
    #pragma unroll
    for (int j = 0; j < CLS; j++) {
        float s = a.x * WlS[(k0 + 0) * CLS + j] + xv.x * WrS[(k0 + 0) * CLS + j];
        s += a.y * WlS[(k0 + 1) * CLS + j] + xv.y * WrS[(k0 + 1) * CLS + j];
        s += a.z * WlS[(k0 + 2) * CLS + j] + xv.z * WrS[(k0 + 2) * CLS + j];
        s += a.w * WlS[(k0 + 3) * CLS + j] + xv.w * WrS[(k0 + 3) * CLS + j];
        c[j] = s;
    }
    #pragma unroll
    for (int j = 0; j < CLS; j++) {
        #pragma unroll
        for (int off = 16; off; off >>= 1)
            c[j] += __shfl_xor_sync(0xffffffffu, c[j], off);
    }
    float ss = 0.0f;
    #pragma unroll
    for (int j = 0; j < CLS; j++) { c[j] += bS[j]; ss += c[j] * c[j]; }
    float rn = rsqrtf(ss);
    int g = __ldg(bp + w);
    if (lane < CLS) atomicAdd(&g_gsum[g * CLS + lane], c[lane] * rn);
    if (lane == 0) atomicAdd(&g_gcnt[g], 1);
}

__global__ void final_kernel(float* __restrict__ out, int G) {
    int g = blockIdx.x * blockDim.x + threadIdx.x;
    if (g >= G) return;
    int cnt = g_gcnt[g];
    float inv = cnt > 0 ? 1.0f / (float)cnt : 0.0f;
    float v[CLS];
    float mx = -1e30f;
    #pragma unroll
    for (int j = 0; j < CLS; j++) { v[j] = g_gsum[g * CLS + j] * inv; mx = fmaxf(mx, v[j]); }
    float s = 0.0f;
    #pragma unroll
    for (int j = 0; j < CLS; j++) s += expf(v[j] - mx);
    float lse = logf(s) + mx;
    #pragma unroll
    for (int j = 0; j < CLS; j++) out[g * CLS + j] = v[j] - lse;
}

// ---------------- launch ---------------------------------------------------------
extern "C" void kernel_launch(void* const* d_in, const int* in_sizes, int n_in,
                              void* d_out, int out_size) {
    const float* x     = (const float*)d_in[0];
    const float* Wl_in = (const float*)d_in[1];
    const float* Wr_in = (const float*)d_in[2];
    const float* b_in  = (const float*)d_in[3];
    const float* Wl_h  = (const float*)d_in[4];
    const float* Wr_h  = (const float*)d_in[5];
    const float* b_h   = (const float*)d_in[6];
    const float* Wl_o  = (const float*)d_in[7];
    const float* Wr_o  = (const float*)d_in[8];
    const float* b_o   = (const float*)d_in[9];
    const int* esrc = (const int*)d_in[10];
    const int* edst = (const int*)d_in[11];
    const int* ca   = (const int*)d_in[12];
    const int* bp   = (const int*)d_in[13];

    int n  = in_sizes[0] / HID;
    int E  = in_sizes[10];
    int Cc = in_sizes[13];
    int G  = out_size / CLS;
    int m  = n + Cc;
    float* out = (float*)d_out;

    void *p_cnt, *p_off, *p_cur, *p_bsum, *p_gsum, *p_gcnt;
    void *p_h1, *p_h2, *p_xb, *p_h1b, *p_bfrag;
    cudaGetSymbolAddress(&p_cnt,   g_cnt);
    cudaGetSymbolAddress(&p_off,   g_off);
    cudaGetSymbolAddress(&p_cur,   g_cur);
    cudaGetSymbolAddress(&p_bsum,  g_bsum);
    cudaGetSymbolAddress(&p_gsum,  g_gsum);
    cudaGetSymbolAddress(&p_gcnt,  g_gcnt);
    cudaGetSymbolAddress(&p_h1,    g_h1);
    cudaGetSymbolAddress(&p_h2,    g_h2);
    cudaGetSymbolAddress(&p_xb,    g_xb);
    cudaGetSymbolAddress(&p_h1b,   g_h1b);
    cudaGetSymbolAddress(&p_bfrag, g_bfrag);

    cudaFuncSetAttribute(node_layer_fused,
                         cudaFuncAttributeMaxDynamicSharedMemorySize, SMEM_NODE);

    cudaMemsetAsync(p_cnt,  0, (size_t)m * sizeof(int));
    cudaMemsetAsync(p_gsum, 0, (size_t)G * CLS * sizeof(float));
    cudaMemsetAsync(p_gcnt, 0, (size_t)G * sizeof(int));

    // prep: weight fragments (tf32) + bf16 x table
    prep_bfrag<<<128, 256>>>(Wl_in, Wr_in, Wl_h, Wr_h);
    prep_xb<<<(n * 32 + 255) / 256, 256>>>(x, (uint2*)p_xb, n * 32);

    // combined CSR build (edges by dst + nodes by cluster)
    int cover = (E > n) ? E : n;
    count_kernel<<<(cover + 255) / 256, 256>>>(edst, ca, E, n);
    int nb = (m + SCAN_B - 1) / SCAN_B;
    scan_partial<<<nb, SCAN_B>>>((const int*)p_cnt, (int*)p_off, (int*)p_bsum, m);
    scan_bsums<<<1, 1024>>>((int*)p_bsum, nb);
    scan_add<<<nb, SCAN_B>>>((const int*)p_cnt, (int*)p_off, (int*)p_bsum, m);
    cudaMemcpyAsync(p_cur, p_off, (size_t)m * sizeof(int), cudaMemcpyDeviceToDevice);
    fill_kernel<<<(cover + 255) / 256, 256>>>(esrc, edst, ca, E, n);

    const float2* bfrag = (const float2*)p_bfrag;
    int gblocks = (n + 127) / 128;

    // layer 1: gather from bf16 x, self from fp32 x
    node_layer_fused<<<gblocks, 256, SMEM_NODE>>>(
        (const uint2*)p_xb, x, bfrag, bfrag + 16 * 16 * 32, b_in,
        (float*)p_h1, (uint32_t*)p_h1b, n);
    // layer 2
    node_layer_fused<<<gblocks, 256, SMEM_NODE>>>(
        (const uint2*)p_h1b, (const float*)p_h1,
        bfrag + 2 * 16 * 16 * 32, bfrag + 3 * 16 * 16 * 32, b_h,
        (float*)p_h2, (uint32_t*)p_xb /* reuse as h2b, unused later */, n);

    // cluster stage
    xc_kernel<<<(Cc + 7) / 8, 256>>>(n, E, Cc);
    cluster_fused_kernel<<<(Cc + 7) / 8, 256>>>(Wl_o, Wr_o, b_o, ca, bp, n, E, Cc);

    final_kernel<<<(G + 63) / 64, 64>>>(out, G);
}

// round 5
// speedup vs baseline: 2.7217x; 1.0225x over previous
#include <cuda_runtime.h>
#include <cuda_bf16.h>
#include <math.h>
#include <stdint.h>

#define HID 128
#define CLS 10
#define NMAX 100000
#define EMAX 1600000
#define CMAX 50000
#define GMAX 64
#define SCAN_B 256
#define MTOT (NMAX + CMAX)
#define NTILES 1024

typedef unsigned long long ull;

// ---------------- scratch (device globals) -----------------------------------
__device__ __align__(256) float g_h1[(size_t)NMAX * HID];   // fp32 layer-1 output
__device__ __align__(256) float g_h2[(size_t)NMAX * HID];   // fp32 layer-2 output
__device__ __align__(256) float g_xc[(size_t)CMAX * HID];   // fp32 cluster means
__device__ __align__(16) uint32_t g_xb [(size_t)NMAX * 64]; // bf16 x table
__device__ __align__(16) uint32_t g_h1b[(size_t)NMAX * 64]; // bf16 h1 table
__device__ __align__(16) uint32_t g_xcb[(size_t)CMAX * 64]; // bf16 xc table
__device__ __align__(16) float2 g_bfrag[4 * 16 * 16 * 32];  // tf32 B fragments
__device__ int g_off[MTOT + 1];
__device__ int g_cur[MTOT];
__device__ int g_esrt[EMAX];           // src ids sorted by dst
__device__ int g_cnodes[NMAX];         // node ids sorted by cluster

// single zeroed region: [cnt MTOT][tstate NTILES][gsum G*CLS][gcnt G]
__device__ int g_zero[MTOT + NTILES + GMAX * CLS + GMAX];
#define Zcnt   (g_zero)
#define Ztst   ((unsigned*)(g_zero + MTOT))
#define Zgsum  ((float*)(g_zero + MTOT + NTILES))
#define Zgcnt  (g_zero + MTOT + NTILES + GMAX * CLS)
#define ZTOTAL (MTOT + NTILES + GMAX * CLS + GMAX)

// ---------------- helpers ------------------------------------------------------
__device__ __forceinline__ float tf32r(float f) {
    uint32_t o;
    asm("cvt.rna.tf32.f32 %0, %1;" : "=r"(o) : "f"(f));
    return __uint_as_float(o);
}
__device__ __forceinline__ void mma8(float d[4], const unsigned a[4],
                                     unsigned b0, unsigned b1) {
    asm volatile("mma.sync.aligned.m16n8k8.row.col.f32.tf32.tf32.f32 "
                 "{%0,%1,%2,%3}, {%4,%5,%6,%7}, {%8,%9}, {%0,%1,%2,%3};"
                 : "+f"(d[0]), "+f"(d[1]), "+f"(d[2]), "+f"(d[3])
                 : "r"(a[0]), "r"(a[1]), "r"(a[2]), "r"(a[3]), "r"(b0), "r"(b1));
}
__device__ __forceinline__ void bf16acc(float4& acc, uint2 u) {
    float2 p = __bfloat1622float2(*(__nv_bfloat162*)&u.x);
    float2 q = __bfloat1622float2(*(__nv_bfloat162*)&u.y);
    acc.x += p.x; acc.y += p.y; acc.z += q.x; acc.w += q.y;
}
__device__ __forceinline__ void st_rel(unsigned* p, unsigned v) {
    asm volatile("st.release.gpu.u32 [%0], %1;" :: "l"(p), "r"(v) : "memory");
}
__device__ __forceinline__ unsigned ld_acq(unsigned* p) {
    unsigned v;
    asm volatile("ld.acquire.gpu.u32 %0, [%1];" : "=r"(v) : "l"(p) : "memory");
    return v;
}

// ---------------- prep: weight fragments + bf16 x table ------------------------
__global__ void prep_kernel(const float* __restrict__ W0, const float* __restrict__ W1,
                            const float* __restrict__ W2, const float* __restrict__ W3,
                            const float* __restrict__ x, uint2* __restrict__ xb, int n) {
    int i = blockIdx.x * blockDim.x + threadIdx.x;
    if (i < 4 * 16 * 16 * 32) {
        int lane = i & 31, nt = (i >> 5) & 15, ks = (i >> 9) & 15, mat = i >> 13;
        const float* W = (mat == 0) ? W0 : (mat == 1) ? W1 : (mat == 2) ? W2 : W3;
        int k0 = ks * 8 + (lane & 3);
        int nn = nt * 8 + (lane >> 2);
        float2 o;
        o.x = tf32r(W[(size_t)k0 * HID + nn]);
        o.y = tf32r(W[(size_t)(k0 + 4) * HID + nn]);
        g_bfrag[i] = o;
    }
    int j = i - 4 * 16 * 16 * 32;
    if (j >= 0 && j < n * 32) {
        float4 v = *(const float4*)(x + (size_t)j * 4);
        __nv_bfloat162 lo = __floats2bfloat162_rn(v.x, v.y);
        __nv_bfloat162 hi = __floats2bfloat162_rn(v.z, v.w);
        uint2 o;
        o.x = *(uint32_t*)&lo;
        o.y = *(uint32_t*)&hi;
        xb[j] = o;
    }
}

// ---------------- histogram (edges by dst + nodes by cluster, combined) --------
__global__ void count_kernel(const int* __restrict__ dst,
                             const int* __restrict__ ca, int E, int n) {
    int i = blockIdx.x * blockDim.x + threadIdx.x;
    if (i < E) atomicAdd(&Zcnt[dst[i]], 1);
    if (i < n) atomicAdd(&Zcnt[n + ca[i]], 1);
}

// ---------------- single-pass decoupled-lookback exclusive scan -----------------
// state: 0 = pending, (1<<30)|agg = aggregate ready, (2<<30)|pre = prefix ready
__global__ void scan_lookback(const int* __restrict__ in, int* __restrict__ off,
                              int* __restrict__ cur, int m) {
    __shared__ int sh[SCAN_B];
    __shared__ int s_prev;
    int b = blockIdx.x;
    int i = b * SCAN_B + threadIdx.x;
    int v = (i < m) ? in[i] : 0;
    sh[threadIdx.x] = v;
    __syncthreads();
    #pragma unroll
    for (int o = 1; o < SCAN_B; o <<= 1) {
        int t = (threadIdx.x >= o) ? sh[threadIdx.x - o] : 0;
        __syncthreads();
        sh[threadIdx.x] += t;
        __syncthreads();
    }
    int agg = sh[SCAN_B - 1];

    if (threadIdx.x == 0) {
        if (b == 0) {
            st_rel(&Ztst[0], (2u << 30) | (unsigned)agg);
            s_prev = 0;
        } else {
            st_rel(&Ztst[b], (1u << 30) | (unsigned)agg);
            int prev = 0, j = b - 1;
            while (true) {
                unsigned s;
                do { s = ld_acq(&Ztst[j]); } while ((s >> 30) == 0);
                prev += (int)(s & 0x3FFFFFFFu);
                if ((s >> 30) == 2u) break;
                j--;
            }
            st_rel(&Ztst[b], (2u << 30) | (unsigned)(prev + agg));
            s_prev = prev;
        }
    }
    __syncthreads();
    int excl = s_prev + sh[threadIdx.x] - v;
    if (i < m) {
        off[i] = excl;
        cur[i] = excl;
        if (i == m - 1) off[m] = excl + v;
    }
}

// ---------------- fill both CSR payloads ----------------------------------------
__global__ void fill_kernel(const int* __restrict__ src, const int* __restrict__ dst,
                            const int* __restrict__ ca, int E, int n) {
    int i = blockIdx.x * blockDim.x + threadIdx.x;
    if (i < E) {
        int d = dst[i];
        int pos = atomicAdd(&g_cur[d], 1);
        g_esrt[pos] = src[i];
    }
    if (i < n) {
        int c = ca[i];
        int pos = atomicAdd(&g_cur[n + c], 1);
        g_cnodes[pos - E] = i;
    }
}

// ---------------- fused node layer: bf16 gather -> tf32 MMA -> norm -------------
#define AFRAG(ks, mt, ln) ((((ks) * 8 + (mt)) * 32 + (ln)) * 4)
#define SMEM_NODE ((16384 + 4096 + 128) * 4)

__global__ __launch_bounds__(256, 2) void node_layer_fused(
    const uint2* __restrict__ xb, const float* __restrict__ xin,
    const float2* __restrict__ bfragL, const float2* __restrict__ bfragR,
    const float* __restrict__ bias,
    float* __restrict__ hout, uint32_t* __restrict__ houtb, int n)
{
    extern __shared__ float sm[];
    float* smx   = sm + 16384;
    float* rowss = sm + 16384 + 4096;
    int tid = threadIdx.x, lane = tid & 31, wid = tid >> 5;
    int n0 = blockIdx.x * 128;
    if (tid < 128) rowss[tid] = 0.0f;

    // ---- gather phase: warp per row, mean of bf16 neighbor rows, write A-frags ----
    for (int r = wid; r < 128; r += 8) {
        int node = n0 + r;
        float4 acc = make_float4(0, 0, 0, 0);
        if (node < n) {
            int off = g_off[node], end = g_off[node + 1];
            int j = off;
            for (; j + 4 <= end; j += 4) {
                int s0 = __ldg(g_esrt + j + 0);
                int s1 = __ldg(g_esrt + j + 1);
                int s2 = __ldg(g_esrt + j + 2);
                int s3 = __ldg(g_esrt + j + 3);
                uint2 u0 = __ldg(xb + (size_t)s0 * 32 + lane);
                uint2 u1 = __ldg(xb + (size_t)s1 * 32 + lane);
                uint2 u2 = __ldg(xb + (size_t)s2 * 32 + lane);
                uint2 u3 = __ldg(xb + (size_t)s3 * 32 + lane);
                bf16acc(acc, u0); bf16acc(acc, u1);
                bf16acc(acc, u2); bf16acc(acc, u3);
            }
            for (; j < end; j++) {
                int s = __ldg(g_esrt + j);
                bf16acc(acc, __ldg(xb + (size_t)s * 32 + lane));
            }
            float inv = (end > off) ? 1.0f / (float)(end - off) : 0.0f;
            acc.x *= inv; acc.y *= inv; acc.z *= inv; acc.w *= inv;
        }
        int mt = r >> 4, w = r & 15, hi = w >> 3, wr = w & 7;
        int comp = 2 * (lane & 1) + hi;
        int kk = lane >> 1;
        float v[4] = {acc.x, acc.y, acc.z, acc.w};
        #pragma unroll
        for (int q = 0; q < 4; q++)
            sm[AFRAG(kk, mt, (wr << 2) | q) + comp] = tf32r(v[q]);
    }
    __syncthreads();

    // ---- MMA phase ----
    int warp_m = wid >> 2, warp_n = wid & 3;
    float d[4][4][4] = {};

    #pragma unroll 2
    for (int ks = 0; ks < 16; ks++) {
        unsigned a[4][4];
        #pragma unroll
        for (int t = 0; t < 4; t++) {
            float4 v = *(float4*)&sm[AFRAG(ks, warp_m * 4 + t, lane)];
            a[t][0] = __float_as_uint(v.x); a[t][1] = __float_as_uint(v.y);
            a[t][2] = __float_as_uint(v.z); a[t][3] = __float_as_uint(v.w);
        }
        #pragma unroll
        for (int u = 0; u < 4; u++) {
            float2 bv = __ldg(&bfragL[(size_t)(ks * 16 + warp_n * 4 + u) * 32 + lane]);
            unsigned b0 = __float_as_uint(bv.x), b1 = __float_as_uint(bv.y);
            #pragma unroll
            for (int t = 0; t < 4; t++) mma8(d[t][u], a[t], b0, b1);
        }
    }

    for (int cc = 0; cc < 4; cc++) {
        __syncthreads();
        #pragma unroll
        for (int e = 0; e < 4; e++) {
            int s = tid + e * 256;
            int kk = s >> 8, mt = (s >> 5) & 7, l = s & 31;
            int r = n0 + mt * 16 + (l >> 2);
            int c = cc * 32 + kk * 8 + (l & 3);
            float v0 = 0, v1 = 0, v2 = 0, v3 = 0;
            if (r < n)     { v0 = xin[(size_t)r * HID + c];       v2 = xin[(size_t)r * HID + c + 4]; }
            if (r + 8 < n) { v1 = xin[(size_t)(r + 8) * HID + c]; v3 = xin[(size_t)(r + 8) * HID + c + 4]; }
            float4 o = make_float4(tf32r(v0), tf32r(v1), tf32r(v2), tf32r(v3));
            *(float4*)&smx[AFRAG(kk, mt, l)] = o;
        }
        __syncthreads();
        #pragma unroll
        for (int kk = 0; kk < 4; kk++) {
            unsigned a[4][4];
            #pragma unroll
            for (int t = 0; t < 4; t++) {
                float4 v = *(float4*)&smx[AFRAG(kk, warp_m * 4 + t, lane)];
                a[t][0] = __float_as_uint(v.x); a[t][1] = __float_as_uint(v.y);
                a[t][2] = __float_as_uint(v.z); a[t][3] = __float_as_uint(v.w);
            }
            int ksg = cc * 4 + kk;
            #pragma unroll
            for (int u = 0; u < 4; u++) {
                float2 bv = __ldg(&bfragR[(size_t)(ksg * 16 + warp_n * 4 + u) * 32 + lane]);
                unsigned b0 = __float_as_uint(bv.x), b1 = __float_as_uint(bv.y);
                #pragma unroll
                for (int t = 0; t < 4; t++) mma8(d[t][u], a[t], b0, b1);
            }
        }
    }

    // ---- epilogue ----
    float2 bb[4];
    #pragma unroll
    for (int u = 0; u < 4; u++)
        bb[u] = *(const float2*)(bias + warp_n * 32 + u * 8 + (lane & 3) * 2);

    #pragma unroll
    for (int t = 0; t < 4; t++) {
        float ss0 = 0, ss1 = 0;
        #pragma unroll
        for (int u = 0; u < 4; u++) {
            float c0 = fmaxf(d[t][u][0] + bb[u].x, 0.0f);
            float c1 = fmaxf(d[t][u][1] + bb[u].y, 0.0f);
            float c2 = fmaxf(d[t][u][2] + bb[u].x, 0.0f);
            float c3 = fmaxf(d[t][u][3] + bb[u].y, 0.0f);
            ss0 += c0 * c0 + c1 * c1;
            ss1 += c2 * c2 + c3 * c3;
            d[t][u][0] = c0; d[t][u][1] = c1; d[t][u][2] = c2; d[t][u][3] = c3;
        }
        int lr = warp_m * 64 + t * 16 + (lane >> 2);
        atomicAdd(&rowss[lr], ss0);
        atomicAdd(&rowss[lr + 8], ss1);
    }
    __syncthreads();

    #pragma unroll
    for (int t = 0; t < 4; t++) {
        int lr = warp_m * 64 + t * 16 + (lane >> 2);
        int r0 = n0 + lr;
        float rn0 = rsqrtf(rowss[lr]);
        float rn1 = rsqrtf(rowss[lr + 8]);
        #pragma unroll
        for (int u = 0; u < 4; u++) {
            int cb = warp_n * 32 + u * 8 + (lane & 3) * 2;
            if (r0 < n) {
                float o0 = d[t][u][0] * rn0, o1 = d[t][u][1] * rn0;
                *(float2*)&hout[(size_t)r0 * HID + cb] = make_float2(o0, o1);
                __nv_bfloat162 bh = __floats2bfloat162_rn(o0, o1);
                houtb[(size_t)r0 * 64 + (cb >> 1)] = *(uint32_t*)&bh;
            }
            if (r0 + 8 < n) {
                float o0 = d[t][u][2] * rn1, o1 = d[t][u][3] * rn1;
                *(float2*)&hout[(size_t)(r0 + 8) * HID + cb] = make_float2(o0, o1);
                __nv_bfloat162 bh = __floats2bfloat162_rn(o0, o1);
                houtb[(size_t)(r0 + 8) * 64 + (cb >> 1)] = *(uint32_t*)&bh;
            }
        }
    }
}

// ---------------- cluster mean: warp per cluster --------------------------------
__global__ void xc_kernel(int n, int E, int Cc) {
    int w = (int)(((unsigned)blockIdx.x * blockDim.x + threadIdx.x) >> 5);
    if (w >= Cc) return;
    int lane = threadIdx.x & 31;
    int mb = g_off[n + w] - E, me = g_off[n + w + 1] - E;
    float4 acc = make_float4(0, 0, 0, 0);
    for (int mi = mb; mi < me; mi++) {
        int node = g_cnodes[mi];
        float4 v = *(const float4*)(g_h2 + (size_t)node * HID + lane * 4);
        acc.x += v.x; acc.y += v.y; acc.z += v.z; acc.w += v.w;
    }
    float inv = (me > mb) ? 1.0f / (float)(me - mb) : 0.0f;
    acc.x *= inv; acc.y *= inv; acc.z *= inv; acc.w *= inv;
    *(float4*)(g_xc + (size_t)w * HID + lane * 4) = acc;
    __nv_bfloat162 lo = __floats2bfloat162_rn(acc.x, acc.y);
    __nv_bfloat162 hi = __floats2bfloat162_rn(acc.z, acc.w);
    uint2 o;
    o.x = *(uint32_t*)&lo;
    o.y = *(uint32_t*)&hi;
    *(uint2*)&g_xcb[(size_t)w * 64 + lane * 2] = o;
}

// ---------------- fused cluster layer: SMEM-hash dedup + MLP-4 gather -----------
__global__ __launch_bounds__(256) void cluster_fused_kernel(
    const float* __restrict__ Wl, const float* __restrict__ Wr,
    const float* __restrict__ b, const int* __restrict__ ca,
    const int* __restrict__ bp, int n, int E, int Cc)
{
    __shared__ float WlS[HID * CLS];
    __shared__ float WrS[HID * CLS];
    __shared__ float bS[CLS];
    __shared__ int hsh[8][512];

    int tid = threadIdx.x;
    int lane = tid & 31, wid = tid >> 5;

    for (int i = tid; i < HID * CLS; i += blockDim.x) {
        WlS[i] = Wl[i];
        WrS[i] = Wr[i];
    }
    if (tid < CLS) bS[tid] = b[tid];
    for (int i = lane; i < 512; i += 32) hsh[wid][i] = 0;
    __syncthreads();

    int w = (int)(((unsigned)blockIdx.x * blockDim.x + tid) >> 5);
    if (w >= Cc) return;

    const uint2* xcb = (const uint2*)g_xcb;
    float4 acc = make_float4(0, 0, 0, 0);
    int nuniq = 0;
    int mb = g_off[n + w] - E, me = g_off[n + w + 1] - E;
    for (int mi = mb; mi < me; mi++) {
        int node = g_cnodes[mi];
        int eb = g_off[node], ee = g_off[node + 1];
        for (int j0 = eb; j0 < ee; j0 += 32) {
            int j = j0 + lane;
            int isnew = 0, cu = 0;
            if (j < ee) {
                int s = g_esrt[j];
                cu = __ldg(ca + s);
                int key = cu + 1;
                unsigned h = ((unsigned)cu * 2654435761u) >> 23;
                h &= 511;
                while (true) {
                    int old = atomicCAS(&hsh[wid][h], 0, key);
                    if (old == 0) { isnew = 1; break; }
                    if (old == key) break;
                    h = (h + 1) & 511;
                }
            }
            unsigned m = __ballot_sync(0xffffffffu, isnew);
            nuniq += __popc(m);
            // MLP-4: issue up to 4 independent row gathers per iteration
            while (m) {
                int b0 = __ffs(m) - 1;             m &= m - 1;
                int b1 = m ? __ffs(m) - 1 : 32; if (b1 < 32) m &= m - 1;
                int b2 = m ? __ffs(m) - 1 : 32; if (b2 < 32) m &= m - 1;
                int b3 = m ? __ffs(m) - 1 : 32; if (b3 < 32) m &= m - 1;
                int c0 = __shfl_sync(0xffffffffu, cu, b0);
                int c1 = __shfl_sync(0xffffffffu, cu, b1 & 31);
                int c2 = __shfl_sync(0xffffffffu, cu, b2 & 31);
                int c3 = __shfl_sync(0xffffffffu, cu, b3 & 31);
                uint2 u0 = __ldg(xcb + (size_t)c0 * 32 + lane);
                uint2 u1 = make_uint2(0, 0), u2 = make_uint2(0, 0), u3 = make_uint2(0, 0);
                if (b1 < 32) u1 = __ldg(xcb + (size_t)c1 * 32 + lane);
                if (b2 < 32) u2 = __ldg(xcb + (size_t)c2 * 32 + lane);
                if (b3 < 32) u3 = __ldg(xcb + (size_t)c3 * 32 + lane);
                bf16acc(acc, u0);
                if (b1 < 32) bf16acc(acc, u1);
                if (b2 < 32) bf16acc(acc, u2);
                if (b3 < 32) bf16acc(acc, u3);
            }
        }
    }
    float inv = nuniq > 0 ? 1.0f / (float)nuniq : 0.0f;
    float4 a = make_float4(acc.x * inv, acc.y * inv, acc.z * inv, acc.w * inv);
    float4 xv = *(const float4*)(g_xc + (size_t)w * HID + lane * 4);

    float c[CLS];
    int k0 = lane * 4;
    #pragma unroll
    for (int j = 0; j < CLS; j++) {
        float s = a.x * WlS[(k0 + 0) * CLS + j] + xv.x * WrS[(k0 + 0) * CLS + j];
        s += a.y * WlS[(k0 + 1) * CLS + j] + xv.y * WrS[(k0 + 1) * CLS + j];
        s += a.z * WlS[(k0 + 2) * CLS + j] + xv.z * WrS[(k0 + 2) * CLS + j];
        s += a.w * WlS[(k0 + 3) * CLS + j] + xv.w * WrS[(k0 + 3) * CLS + j];
        c[j] = s;
    }
    #pragma unroll
    for (int j = 0; j < CLS; j++) {
        #pragma unroll
        for (int off = 16; off; off >>= 1)
            c[j] += __shfl_xor_sync(0xffffffffu, c[j], off);
    }
    float ss = 0.0f;
    #pragma unroll
    for (int j = 0; j < CLS; j++) { c[j] += bS[j]; ss += c[j] * c[j]; }
    float rn = rsqrtf(ss);
    int g = __ldg(bp + w);
    if (lane < CLS) atomicAdd(&Zgsum[g * CLS + lane], c[lane] * rn);
    if (lane == 0) atomicAdd(&Zgcnt[g], 1);
}

__global__ void final_kernel(float* __restrict__ out, int G) {
    int g = blockIdx.x * blockDim.x + threadIdx.x;
    if (g >= G) return;
    int cnt = Zgcnt[g];
    float inv = cnt > 0 ? 1.0f / (float)cnt : 0.0f;
    float v[CLS];
    float mx = -1e30f;
    #pragma unroll
    for (int j = 0; j < CLS; j++) { v[j] = Zgsum[g * CLS + j] * inv; mx = fmaxf(mx, v[j]); }
    float s = 0.0f;
    #pragma unroll
    for (int j = 0; j < CLS; j++) s += expf(v[j] - mx);
    float lse = logf(s) + mx;
    #pragma unroll
    for (int j = 0; j < CLS; j++) out[g * CLS + j] = v[j] - lse;
}

// ---------------- launch ---------------------------------------------------------
extern "C" void kernel_launch(void* const* d_in, const int* in_sizes, int n_in,
                              void* d_out, int out_size) {
    const float* x     = (const float*)d_in[0];
    const float* Wl_in = (const float*)d_in[1];
    const float* Wr_in = (const float*)d_in[2];
    const float* b_in  = (const float*)d_in[3];
    const float* Wl_h  = (const float*)d_in[4];
    const float* Wr_h  = (const float*)d_in[5];
    const float* b_h   = (const float*)d_in[6];
    const float* Wl_o  = (const float*)d_in[7];
    const float* Wr_o  = (const float*)d_in[8];
    const float* b_o   = (const float*)d_in[9];
    const int* esrc = (const int*)d_in[10];
    const int* edst = (const int*)d_in[11];
    const int* ca   = (const int*)d_in[12];
    const int* bp   = (const int*)d_in[13];

    int n  = in_sizes[0] / HID;
    int E  = in_sizes[10];
    int Cc = in_sizes[13];
    int G  = out_size / CLS;
    int m  = n + Cc;
    float* out = (float*)d_out;

    void *p_zero, *p_off, *p_cur, *p_h1, *p_xb, *p_h1b, *p_bfrag;
    cudaGetSymbolAddress(&p_zero,  g_zero);
    cudaGetSymbolAddress(&p_off,   g_off);
    cudaGetSymbolAddress(&p_cur,   g_cur);
    cudaGetSymbolAddress(&p_h1,    g_h1);
    cudaGetSymbolAddress(&p_xb,    g_xb);
    cudaGetSymbolAddress(&p_h1b,   g_h1b);
    cudaGetSymbolAddress(&p_bfrag, g_bfrag);

    cudaFuncSetAttribute(node_layer_fused,
                         cudaFuncAttributeMaxDynamicSharedMemorySize, SMEM_NODE);

    cudaMemsetAsync(p_zero, 0, (size_t)ZTOTAL * sizeof(int));

    int cover = (E > n) ? E : n;
    count_kernel<<<(cover + 255) / 256, 256>>>(edst, ca, E, n);

    int pthreads = 4 * 16 * 16 * 32 + n * 32;
    prep_kernel<<<(pthreads + 255) / 256, 256>>>(Wl_in, Wr_in, Wl_h, Wr_h,
                                                 x, (uint2*)p_xb, n);

    int nb = (m + SCAN_B - 1) / SCAN_B;
    scan_lookback<<<nb, SCAN_B>>>((const int*)p_zero /* = Zcnt */, (int*)p_off,
                                  (int*)p_cur, m);

    fill_kernel<<<(cover + 255) / 256, 256>>>(esrc, edst, ca, E, n);

    const float2* bfrag = (const float2*)p_bfrag;
    int gblocks = (n + 127) / 128;
    void* p_h2;
    cudaGetSymbolAddress(&p_h2, g_h2);

    node_layer_fused<<<gblocks, 256, SMEM_NODE>>>(
        (const uint2*)p_xb, x, bfrag, bfrag + 16 * 16 * 32, b_in,
        (float*)p_h1, (uint32_t*)p_h1b, n);
    node_layer_fused<<<gblocks, 256, SMEM_NODE>>>(
        (const uint2*)p_h1b, (const float*)p_h1,
        bfrag + 2 * 16 * 16 * 32, bfrag + 3 * 16 * 16 * 32, b_h,
        (float*)p_h2, (uint32_t*)p_xb /* reuse, unused later */, n);

    xc_kernel<<<(Cc + 7) / 8, 256>>>(n, E, Cc);
    cluster_fused_kernel<<<(Cc + 7) / 8, 256>>>(Wl_o, Wr_o, b_o, ca, bp, n, E, Cc);

    final_kernel<<<(G + 63) / 64, 64>>>(out, G);
}